// round 13
// baseline (speedup 1.0000x reference)
#include <cuda_runtime.h>
#include <math.h>
#include <stdint.h>

// ---------------- problem constants ----------------
#define Dm   1024
#define Tq   512
#define NB   4
#define NH   16
#define HDm  64
#define KTOT 1792
#define MR   2048        // NB*Tq rows
#define DFF  4096

// ---------------- scratch (device globals; no allocation) ----------------
__device__ float g_mod[NB * 6 * Dm];
__device__ float g_xnorm[MR * Dm];
__device__ float g_q0[MR * Dm];
__device__ float g_qad[3 * MR * Dm];
__device__ float g_hidden[3 * MR * 256];
__device__ float g_kcat[NB * KTOT * Dm];
__device__ float g_vcat[NB * KTOT * Dm];
__device__ float g_attnout[MR * Dm];
__device__ float g_xa[MR * Dm];
__device__ float g_hln[MR * Dm];
__device__ float g_hff[MR * DFF];
__device__ float g_rcos[Tq * 32];
__device__ float g_rsin[Tq * 32];

// ---------------- helpers ----------------
__device__ __forceinline__ void mma8(float* c, const uint32_t* a, const uint32_t* b) {
    asm volatile(
        "mma.sync.aligned.m16n8k8.row.col.f32.tf32.tf32.f32 "
        "{%0,%1,%2,%3},{%4,%5,%6,%7},{%8,%9},{%0,%1,%2,%3};\n"
        : "+f"(c[0]), "+f"(c[1]), "+f"(c[2]), "+f"(c[3])
        : "r"(a[0]), "r"(a[1]), "r"(a[2]), "r"(a[3]), "r"(b[0]), "r"(b[1]));
}

__device__ __forceinline__ void cpa16(uint32_t dst, const void* src) {
    asm volatile("cp.async.cg.shared.global [%0], [%1], 16;\n" :: "r"(dst), "l"(src));
}
#define CP_COMMIT() asm volatile("cp.async.commit_group;\n" ::)
#define CP_WAIT2()  asm volatile("cp.async.wait_group 2;\n" ::: "memory")
#define CP_WAIT0()  asm volatile("cp.async.wait_group 0;\n" ::: "memory")

// ================== tf32 GEMM core: C = A @ W^T + bias (+ epilogue) ==========
// 4-stage cp.async pipeline (prefetch distance 3, wait_group 2 -> DRAM latency
// covered by ~2 compute iterations). Shared layout [m][k], row stride 20:
// fragment-load banks (20g mod 32) + tc fill all 32 banks -> conflict-free.
// tf32 by HW truncation (no cvt).
#define GRS   20
#define GSTG  (128 * GRS)
#define GEMM_SMEM (2 * 4 * GSTG * 4)

template<int EPI, int Kc, int Nc>
__device__ __forceinline__ void gemm_core(
    const float* __restrict__ A, const float* __restrict__ W,
    const float* __restrict__ bias, float* __restrict__ C,
    int Lb, int outBatchRows, int outRowOff,
    const float* __restrict__ res, const float* __restrict__ mod, int gateOff,
    float* sm)
{
    float* As = sm;
    float* Bs = sm + 4 * GSTG;

    int tid  = threadIdx.x;
    int wid  = tid >> 5;
    int lane = tid & 31;
    int g  = lane >> 2;      // 0..7
    int tc = lane & 3;       // 0..3
    int warpM = (wid & 1) * 64;
    int warpN = (wid >> 1) * 32;

    int row0 = blockIdx.y * 128;
    int col0 = blockIdx.x * 128;

    int ldRow = tid >> 1;          // 0..127
    int ldCol = (tid & 1) * 8;     // 0 or 8
    const float* Ag = A + (size_t)(row0 + ldRow) * Kc + ldCol;
    const float* Wg = W + (size_t)(col0 + ldRow) * Kc + ldCol;
    uint32_t sAd = (uint32_t)__cvta_generic_to_shared(As + ldRow * GRS + ldCol);
    uint32_t sBd = (uint32_t)__cvta_generic_to_shared(Bs + ldRow * GRS + ldCol);

    const int NIT = Kc >> 4;

    float acc[4][4][4];
    #pragma unroll
    for (int mi = 0; mi < 4; mi++)
        #pragma unroll
        for (int ni = 0; ni < 4; ni++)
            #pragma unroll
            for (int e = 0; e < 4; e++) acc[mi][ni][e] = 0.f;

    auto issue = [&](int it) {
        uint32_t off = (uint32_t)(it & 3) * (GSTG * 4);
        const float* a = Ag + it * 16;
        const float* w = Wg + it * 16;
        cpa16(sAd + off, a);
        cpa16(sAd + off + 16, a + 4);
        cpa16(sBd + off, w);
        cpa16(sBd + off + 16, w + 4);
    };
    issue(0); CP_COMMIT();
    issue(1); CP_COMMIT();
    issue(2); CP_COMMIT();

    #pragma unroll 1
    for (int it = 0; it < NIT; it++) {
        CP_WAIT2();
        __syncthreads();
        if (it + 3 < NIT) issue(it + 3);
        CP_COMMIT();

        const float* Ast = As + (it & 3) * GSTG;
        const float* Bst = Bs + (it & 3) * GSTG;
        #pragma unroll
        for (int kb = 0; kb < 16; kb += 8) {
            uint32_t af[4][4];
            #pragma unroll
            for (int mi = 0; mi < 4; mi++) {
                int r = warpM + mi * 16 + g;
                af[mi][0] = __float_as_uint(Ast[r * GRS + kb + tc]);
                af[mi][1] = __float_as_uint(Ast[(r + 8) * GRS + kb + tc]);
                af[mi][2] = __float_as_uint(Ast[r * GRS + kb + tc + 4]);
                af[mi][3] = __float_as_uint(Ast[(r + 8) * GRS + kb + tc + 4]);
            }
            uint32_t bf_[4][2];
            #pragma unroll
            for (int ni = 0; ni < 4; ni++) {
                int cN = warpN + ni * 8 + g;
                bf_[ni][0] = __float_as_uint(Bst[cN * GRS + kb + tc]);
                bf_[ni][1] = __float_as_uint(Bst[cN * GRS + kb + tc + 4]);
            }
            #pragma unroll
            for (int mi = 0; mi < 4; mi++)
                #pragma unroll
                for (int ni = 0; ni < 4; ni++)
                    mma8(acc[mi][ni], af[mi], bf_[ni]);
        }
    }

    // epilogue
    #pragma unroll
    for (int mi = 0; mi < 4; mi++) {
        #pragma unroll
        for (int ib = 0; ib < 2; ib++) {
            int m = row0 + warpM + mi * 16 + g + ib * 8;
            int orow = (m / Lb) * outBatchRows + outRowOff + (m % Lb);
            const float* resr = (EPI == 2) ? res + (size_t)m * Nc : nullptr;
            const float* gr   = (EPI == 2) ? mod + (m / Tq) * (6 * Dm) + gateOff : nullptr;
            #pragma unroll
            for (int ni = 0; ni < 4; ni++) {
                int n = col0 + warpN + ni * 8 + tc * 2;
                float v0 = acc[mi][ni][ib * 2 + 0] + bias[n];
                float v1 = acc[mi][ni][ib * 2 + 1] + bias[n + 1];
                if (EPI == 1) {
                    v0 = 0.5f * v0 * (1.f + erff(v0 * 0.70710678118654752f));
                    v1 = 0.5f * v1 * (1.f + erff(v1 * 0.70710678118654752f));
                }
                if (EPI == 2) {
                    v0 = resr[n] + gr[n] * v0;
                    v1 = resr[n + 1] + gr[n + 1] * v1;
                }
                float2 o2 = {v0, v1};
                *(float2*)&C[(size_t)orow * Nc + n] = o2;
            }
        }
    }
}

// ---- batched K/V/Q + adapter_h: z=0..3 K, 4..7 V, 8 Q, 9..11 adapter_h ----
__global__ __launch_bounds__(256, 2) void kvq_kernel(
    const float* __restrict__ xnorm, const float* __restrict__ bev,
    const float* __restrict__ vl, const float* __restrict__ reas,
    const float* __restrict__ k_w, const float* __restrict__ k_b,
    const float* __restrict__ v_w, const float* __restrict__ v_b,
    const float* __restrict__ qw, const float* __restrict__ qb,
    const float* __restrict__ qa_w, const float* __restrict__ qa_b,
    float* __restrict__ kcat, float* __restrict__ vcat,
    float* __restrict__ q0, float* __restrict__ hidden)
{
    extern __shared__ float smg[];
    int z = blockIdx.z;
    if (z >= 9) {
        int a = z - 9;
        if (blockIdx.x >= 2) return;
        gemm_core<0, 1024, 256>(xnorm, qa_w + (size_t)a * 256 * Dm, qa_b + a * 256,
                                hidden + (size_t)a * MR * 256,
                                1 << 30, 0, 0, nullptr, nullptr, 0, smg);
        return;
    }
    const float* A; const float* W; const float* bias; float* C;
    int Lb, oBR, oRO;
    if (z < 8) {
        int src = z & 3;
        if (src == 3 && blockIdx.y >= 8) return;
        A = (src == 0) ? xnorm : (src == 1) ? bev : (src == 2) ? vl : reas;
        bool isV = z >= 4;
        W    = (isV ? v_w : k_w) + (size_t)src * Dm * Dm;
        bias = (isV ? v_b : k_b) + src * Dm;
        C    = isV ? vcat : kcat;
        Lb = (src == 3) ? 256 : 512;
        oBR = KTOT; oRO = src * 512;
    } else {
        A = xnorm; W = qw; bias = qb; C = q0;
        Lb = 1 << 30; oBR = 0; oRO = 0;
    }
    gemm_core<0, 1024, 1024>(A, W, bias, C, Lb, oBR, oRO, nullptr, nullptr, 0, smg);
}

// ---- batched adapter out: z = 0..2 ----
__global__ __launch_bounds__(256, 2) void adapter_o_kernel(
    const float* __restrict__ hidden, const float* __restrict__ qa_out_w,
    const float* __restrict__ qa_out_b, float* __restrict__ qad)
{
    extern __shared__ float smg[];
    int z = blockIdx.z;
    gemm_core<0, 256, 1024>(hidden + (size_t)z * MR * 256, qa_out_w, qa_out_b,
                            qad + (size_t)z * MR * Dm,
                            1 << 30, 0, 0, nullptr, nullptr, 0, smg);
}

// ---- generic (identity remap) GEMM ----
template<int EPI, int Kc, int Nc>
__global__ __launch_bounds__(256, 2) void gemm_kernel(
    const float* __restrict__ A, const float* __restrict__ W,
    const float* __restrict__ bias, float* __restrict__ C,
    const float* __restrict__ res, const float* __restrict__ mod, int gateOff)
{
    extern __shared__ float smg[];
    gemm_core<EPI, Kc, Nc>(A, W, bias, C, 1 << 30, 0, 0, res, mod, gateOff, smg);
}

// ---------------- mod = silu(cond) @ adaln_w^T + adaln_b ----------------
__global__ __launch_bounds__(256) void mod_kernel(const float* __restrict__ cond,
                                                  const float* __restrict__ W,
                                                  const float* __restrict__ bb,
                                                  float* __restrict__ mod)
{
    int b = blockIdx.y;
    __shared__ float sc[Dm];
    for (int i = threadIdx.x; i < Dm; i += 256) {
        float c = cond[b * Dm + i];
        sc[i] = c / (1.f + expf(-c));
    }
    __syncthreads();
    int w = threadIdx.x >> 5, lane = threadIdx.x & 31;
    int n = blockIdx.x * 8 + w;
    const float* wr = W + (size_t)n * Dm;
    float acc = 0.f;
    for (int k = lane; k < Dm; k += 32) acc += sc[k] * wr[k];
    #pragma unroll
    for (int o = 16; o; o >>= 1) acc += __shfl_xor_sync(~0u, acc, o);
    if (lane == 0) mod[b * 6 * Dm + n] = acc + bb[n];
}

// ---------------- LayerNorm + AdaLN modulate ----------------
__global__ __launch_bounds__(256) void ln_mod_kernel(const float* __restrict__ x,
                                                     const float* __restrict__ w,
                                                     const float* __restrict__ bvec,
                                                     const float* __restrict__ mod,
                                                     int shiftOff, int scaleOff,
                                                     float* __restrict__ out)
{
    int row = blockIdx.x;
    int tid = threadIdx.x;
    float4 v = ((const float4*)(x + (size_t)row * Dm))[tid];
    float s = v.x + v.y + v.z + v.w;
    float q = v.x * v.x + v.y * v.y + v.z * v.z + v.w * v.w;
    __shared__ float rs[8], rq[8];
    #pragma unroll
    for (int o = 16; o; o >>= 1) {
        s += __shfl_xor_sync(~0u, s, o);
        q += __shfl_xor_sync(~0u, q, o);
    }
    if ((tid & 31) == 0) { rs[tid >> 5] = s; rq[tid >> 5] = q; }
    __syncthreads();
    float sum = 0.f, sq = 0.f;
    #pragma unroll
    for (int i = 0; i < 8; i++) { sum += rs[i]; sq += rq[i]; }
    float mean = sum * (1.f / Dm);
    float var  = sq * (1.f / Dm) - mean * mean;
    float inv  = rsqrtf(var + 1e-5f);
    const float* ms = mod + (row / Tq) * (6 * Dm);
    int d = tid * 4;
    float in[4] = {v.x, v.y, v.z, v.w};
    float4 ov;
    float* po = (float*)&ov;
    #pragma unroll
    for (int e = 0; e < 4; e++) {
        float xn = (in[e] - mean) * inv * w[d + e] + bvec[d + e];
        po[e] = xn * (1.f + ms[scaleOff + d + e]) + ms[shiftOff + d + e];
    }
    ((float4*)(out + (size_t)row * Dm))[tid] = ov;
}

// ---------------- RoPE table ----------------
__global__ void rope_table_kernel(float* __restrict__ c, float* __restrict__ s)
{
    int pos = blockIdx.x, j = threadIdx.x;
    float ang = (float)pos * expf(-(float)j * (9.2103403719761836f / 32.f));
    float sn, cs;
    sincosf(ang, &sn, &cs);
    c[pos * 32 + j] = cs;
    s[pos * 32 + j] = sn;
}

// -------- QK post, merged: q0 rows [0,MR), qad [MR,4MR), kcat [4MR,4MR+NB*KTOT)
__global__ __launch_bounds__(256) void qkpost_all_kernel(
    float* __restrict__ q0, float* __restrict__ qad, float* __restrict__ kcat,
    const float* __restrict__ qn_w, const float* __restrict__ kn_w,
    const float* __restrict__ rc, const float* __restrict__ rs)
{
    int row = blockIdx.x, tid = threadIdx.x;
    float* rp;
    const float* w;
    int pos;
    if (row < MR) {
        rp = q0 + (size_t)row * Dm; w = qn_w; pos = row & (Tq - 1);
    } else if (row < 4 * MR) {
        rp = qad + (size_t)(row - MR) * Dm; w = qn_w; pos = -1;
    } else {
        int r = row - 4 * MR;
        rp = kcat + (size_t)r * Dm; w = kn_w;
        int rr = r % KTOT;
        pos = (rr < 512) ? rr : (rr < 1024) ? rr - 512 : (rr < 1536) ? rr - 1024 : rr - 1536;
    }
    float4 v = ((float4*)rp)[tid];
    float ss = v.x * v.x + v.y * v.y + v.z * v.z + v.w * v.w;
    ss += __shfl_xor_sync(~0u, ss, 1, 16);
    ss += __shfl_xor_sync(~0u, ss, 2, 16);
    ss += __shfl_xor_sync(~0u, ss, 4, 16);
    ss += __shfl_xor_sync(~0u, ss, 8, 16);
    float inv = rsqrtf(ss * (1.f / 64.f) + 1e-6f);
    int dl = (tid & 15) * 4;
    float nv[4] = {v.x * inv * w[dl], v.y * inv * w[dl + 1],
                   v.z * inv * w[dl + 2], v.w * inv * w[dl + 3]};
    if (pos >= 0) {
        float pv[4];
        #pragma unroll
        for (int e = 0; e < 4; e++) pv[e] = __shfl_xor_sync(~0u, nv[e], 8, 16);
        bool firstHalf = dl < 32;
        int jb = dl & 31;
        float4 c4 = *(const float4*)&rc[pos * 32 + jb];
        float4 s4 = *(const float4*)&rs[pos * 32 + jb];
        float cse[4] = {c4.x, c4.y, c4.z, c4.w};
        float sne[4] = {s4.x, s4.y, s4.z, s4.w};
        #pragma unroll
        for (int e = 0; e < 4; e++) {
            nv[e] = firstHalf ? (nv[e] * cse[e] - pv[e] * sne[e])
                              : (nv[e] * cse[e] + pv[e] * sne[e]);
        }
    }
    float4 o = {nv[0], nv[1], nv[2], nv[3]};
    ((float4*)rp)[tid] = o;
}

// ============ Flash attention, tf32 mma + cp.async double-buffered K/V ======
// 128 queries x 1 head per CTA (256 threads, 8 warps, 16q x 64kk warp tile).
// K/V tiles contiguous across segments -> single prefetch stream. Layouts:
// Qs/Ks stride 84, Vs stride 72 (bank-conflict-free fragment loads).
#define QKS 84
#define VS  72
#define KVSTG (64 * QKS + 64 * VS)
#define FLASH_SMEM ((128 * QKS + 2 * KVSTG) * 4)

__global__ __launch_bounds__(256) void flash_mma_kernel(
    const float* __restrict__ q0p, const float* __restrict__ q1p,
    const float* __restrict__ q2p, const float* __restrict__ q3p,
    const float* __restrict__ kcat, const float* __restrict__ vcat,
    const float* __restrict__ temps, const float* __restrict__ sbias,
    const float* __restrict__ gating, float* __restrict__ outp)
{
    extern __shared__ float sm[];
    float* Qs  = sm;                    // [128][84]
    float* KV0 = sm + 128 * QKS;        // stage 0: K [64][84] + V [64][72]
    float* KV1 = KV0 + KVSTG;           // stage 1

    int tid = threadIdx.x;
    int wid = tid >> 5, lane = tid & 31;
    int g = lane >> 2, tc = lane & 3;
    int q0w = wid * 16;                 // 0..112
    int h = blockIdx.y, b = blockIdx.z;
    int qbase = b * Tq + blockIdx.x * 128;

    const float* qp[4] = {q0p, q1p, q2p, q3p};
    float rg = tanhf(gating[0]);

    float m0 = -1e30f, m1 = -1e30f, l0 = 0.f, l1 = 0.f;
    float Oacc[8][4];
    #pragma unroll
    for (int dt = 0; dt < 8; dt++)
        #pragma unroll
        for (int e = 0; e < 4; e++) Oacc[dt][e] = 0.f;

    // KV staging: 256 threads cover 64 rows x 64 d; 16 floats each
    int sr  = tid & 63;
    int scb = (tid >> 6) * 16;          // 0,16,32,48
    uint32_t kd0 = (uint32_t)__cvta_generic_to_shared(KV0 + sr * QKS + scb);
    uint32_t vd0 = (uint32_t)__cvta_generic_to_shared(KV0 + 64 * QKS + sr * VS + scb);
    const float* srcK0 = kcat + (size_t)(b * KTOT + sr) * Dm + h * HDm + scb;
    const float* srcV0 = vcat + (size_t)(b * KTOT + sr) * Dm + h * HDm + scb;

    // Q staging: 256 threads cover 128 rows x 64 d; 32 floats each
    int qr  = tid >> 1;
    int qcb = (tid & 1) * 32;

    int srcA = (lane & ~3) | (tc >> 1);
    int srcB = srcA + 2;
    bool odd = tc & 1;

    auto issue_kv = [&](int t) {
        uint32_t off = (uint32_t)(t & 1) * (KVSTG * 4);
        const float* sk = srcK0 + (size_t)t * 64 * Dm;
        const float* sv = srcV0 + (size_t)t * 64 * Dm;
        #pragma unroll
        for (int j = 0; j < 4; j++) {
            cpa16(kd0 + off + j * 16, sk + j * 4);
            cpa16(vd0 + off + j * 16, sv + j * 4);
        }
    };

    issue_kv(0); CP_COMMIT();
    int t = 0;

    for (int seg = 0; seg < 4; seg++) {
        float tt = temps[seg];
        float sp = tt > 20.f ? tt : log1pf(expf(tt));
        float scale = 0.125f * (1.f + sp);
        float sb = sbias[seg];
        if (seg == 3) { scale *= rg; sb *= rg; }

        // stage Q variant (natural [q][d]); Qs untouched by kv pipeline
        __syncthreads();
        {
            const float* src = qp[seg] + (size_t)(qbase + qr) * Dm + h * HDm + qcb;
            float* qd = &Qs[qr * QKS + qcb];
            #pragma unroll
            for (int j4 = 0; j4 < 8; j4++)
                *(float4*)(qd + j4 * 4) = ((const float4*)src)[j4];
        }
        __syncthreads();
        // preload Q fragments (reused for all k-tiles of this segment)
        uint32_t qf[8][4];
        #pragma unroll
        for (int c = 0; c < 8; c++) {
            qf[c][0] = __float_as_uint(Qs[(q0w + g) * QKS + c * 8 + tc]);
            qf[c][1] = __float_as_uint(Qs[(q0w + g + 8) * QKS + c * 8 + tc]);
            qf[c][2] = __float_as_uint(Qs[(q0w + g) * QKS + c * 8 + tc + 4]);
            qf[c][3] = __float_as_uint(Qs[(q0w + g + 8) * QKS + c * 8 + tc + 4]);
        }

        int nt = (seg == 3) ? 4 : 8;
        for (int kt = 0; kt < nt; kt++, t++) {
            CP_WAIT0();
            __syncthreads();
            if (t + 1 < 28) issue_kv(t + 1);
            CP_COMMIT();

            const float* Ks = (t & 1) ? KV1 : KV0;
            const float* Vs = Ks + 64 * QKS;

            // ---- S = Q K^T (16q x 64kk per warp) ----
            float S[8][4];
            #pragma unroll
            for (int ni = 0; ni < 8; ni++)
                #pragma unroll
                for (int e = 0; e < 4; e++) S[ni][e] = 0.f;
            #pragma unroll
            for (int c = 0; c < 8; c++) {
                #pragma unroll
                for (int ni = 0; ni < 8; ni++) {
                    uint32_t bf[2];
                    bf[0] = __float_as_uint(Ks[(ni * 8 + g) * QKS + c * 8 + tc]);
                    bf[1] = __float_as_uint(Ks[(ni * 8 + g) * QKS + c * 8 + tc + 4]);
                    mma8(S[ni], qf[c], bf);
                }
            }

            // ---- online softmax (rows g, g+8 of warp tile) ----
            float r0 = -1e30f, r1 = -1e30f;
            #pragma unroll
            for (int ni = 0; ni < 8; ni++) {
                S[ni][0] = fmaf(S[ni][0], scale, sb);
                S[ni][1] = fmaf(S[ni][1], scale, sb);
                S[ni][2] = fmaf(S[ni][2], scale, sb);
                S[ni][3] = fmaf(S[ni][3], scale, sb);
                r0 = fmaxf(r0, fmaxf(S[ni][0], S[ni][1]));
                r1 = fmaxf(r1, fmaxf(S[ni][2], S[ni][3]));
            }
            r0 = fmaxf(r0, __shfl_xor_sync(~0u, r0, 1));
            r0 = fmaxf(r0, __shfl_xor_sync(~0u, r0, 2));
            r1 = fmaxf(r1, __shfl_xor_sync(~0u, r1, 1));
            r1 = fmaxf(r1, __shfl_xor_sync(~0u, r1, 2));
            float mn0 = fmaxf(m0, r0), mn1 = fmaxf(m1, r1);
            float f0 = __expf(m0 - mn0), f1 = __expf(m1 - mn1);
            float s0 = 0.f, s1 = 0.f;
            #pragma unroll
            for (int ni = 0; ni < 8; ni++) {
                S[ni][0] = __expf(S[ni][0] - mn0);
                S[ni][1] = __expf(S[ni][1] - mn0);
                S[ni][2] = __expf(S[ni][2] - mn1);
                S[ni][3] = __expf(S[ni][3] - mn1);
                s0 += S[ni][0] + S[ni][1];
                s1 += S[ni][2] + S[ni][3];
            }
            s0 += __shfl_xor_sync(~0u, s0, 1);
            s0 += __shfl_xor_sync(~0u, s0, 2);
            s1 += __shfl_xor_sync(~0u, s1, 1);
            s1 += __shfl_xor_sync(~0u, s1, 2);
            l0 = l0 * f0 + s0;
            l1 = l1 * f1 + s1;
            m0 = mn0; m1 = mn1;
            #pragma unroll
            for (int dt = 0; dt < 8; dt++) {
                Oacc[dt][0] *= f0; Oacc[dt][1] *= f0;
                Oacc[dt][2] *= f1; Oacc[dt][3] *= f1;
            }

            // ---- O += P V  (P from registers via lane transpose) ----
            #pragma unroll
            for (int ni = 0; ni < 8; ni++) {
                float p0 = S[ni][0], p1 = S[ni][1];
                float p2 = S[ni][2], p3 = S[ni][3];
                float x0 = __shfl_sync(~0u, p0, srcA), y0 = __shfl_sync(~0u, p1, srcA);
                float x2 = __shfl_sync(~0u, p0, srcB), y2 = __shfl_sync(~0u, p1, srcB);
                float x1 = __shfl_sync(~0u, p2, srcA), y1 = __shfl_sync(~0u, p3, srcA);
                float x3 = __shfl_sync(~0u, p2, srcB), y3 = __shfl_sync(~0u, p3, srcB);
                uint32_t ap[4];
                ap[0] = __float_as_uint(odd ? y0 : x0);
                ap[1] = __float_as_uint(odd ? y1 : x1);
                ap[2] = __float_as_uint(odd ? y2 : x2);
                ap[3] = __float_as_uint(odd ? y3 : x3);
                #pragma unroll
                for (int dt = 0; dt < 8; dt++) {
                    uint32_t bv[2];
                    bv[0] = __float_as_uint(Vs[(ni * 8 + tc) * VS + dt * 8 + g]);
                    bv[1] = __float_as_uint(Vs[(ni * 8 + tc + 4) * VS + dt * 8 + g]);
                    mma8(Oacc[dt], ap, bv);
                }
            }
        }
    }

    float i0 = 1.f / l0, i1 = 1.f / l1;
    int qg0 = qbase + q0w + g, qg1 = qg0 + 8;
    #pragma unroll
    for (int dt = 0; dt < 8; dt++) {
        int dcol = h * HDm + dt * 8 + tc * 2;
        float2 o0 = {Oacc[dt][0] * i0, Oacc[dt][1] * i0};
        float2 o1 = {Oacc[dt][2] * i1, Oacc[dt][3] * i1};
        *(float2*)&outp[(size_t)qg0 * Dm + dcol] = o0;
        *(float2*)&outp[(size_t)qg1 * Dm + dcol] = o1;
    }
}

// ---------------- launch ----------------
static float* symaddr(const void* s) {
    void* p = nullptr;
    cudaGetSymbolAddress(&p, s);
    return (float*)p;
}

extern "C" void kernel_launch(void* const* d_in, const int* in_sizes, int n_in,
                              void* d_out, int out_size)
{
    const float* x        = (const float*)d_in[0];
    const float* bev      = (const float*)d_in[1];
    const float* vl       = (const float*)d_in[2];
    const float* reas     = (const float*)d_in[3];
    const float* cond     = (const float*)d_in[4];
    const float* ln_pre_w = (const float*)d_in[5];
    const float* ln_pre_b = (const float*)d_in[6];
    const float* adaln_w  = (const float*)d_in[7];
    const float* adaln_b  = (const float*)d_in[8];
    const float* q_proj_w = (const float*)d_in[9];
    const float* q_proj_b = (const float*)d_in[10];
    const float* qa_w     = (const float*)d_in[11];
    const float* qa_b     = (const float*)d_in[12];
    const float* qa_out_w = (const float*)d_in[13];
    const float* qa_out_b = (const float*)d_in[14];
    const float* k_w      = (const float*)d_in[15];
    const float* k_b      = (const float*)d_in[16];
    const float* v_w      = (const float*)d_in[17];
    const float* v_b      = (const float*)d_in[18];
    const float* o_w      = (const float*)d_in[19];
    const float* o_b      = (const float*)d_in[20];
    const float* qn_w     = (const float*)d_in[21];
    const float* kn_w     = (const float*)d_in[22];
    const float* gating   = (const float*)d_in[23];
    const float* temps    = (const float*)d_in[24];
    const float* sbias    = (const float*)d_in[25];
    const float* ffn_ln_w = (const float*)d_in[26];
    const float* ffn_ln_b = (const float*)d_in[27];
    const float* ffn_w1   = (const float*)d_in[28];
    const float* ffn_b1   = (const float*)d_in[29];
    const float* ffn_w2   = (const float*)d_in[30];
    const float* ffn_b2   = (const float*)d_in[31];
    float* out = (float*)d_out;

    float* p_mod    = symaddr(g_mod);
    float* p_xnorm  = symaddr(g_xnorm);
    float* p_q0     = symaddr(g_q0);
    float* p_qad    = symaddr(g_qad);
    float* p_hidden = symaddr(g_hidden);
    float* p_kcat   = symaddr(g_kcat);
    float* p_vcat   = symaddr(g_vcat);
    float* p_attn   = symaddr(g_attnout);
    float* p_xa     = symaddr(g_xa);
    float* p_hln    = symaddr(g_hln);
    float* p_hff    = symaddr(g_hff);
    float* p_rcos   = symaddr(g_rcos);
    float* p_rsin   = symaddr(g_rsin);

    cudaFuncSetAttribute(kvq_kernel, cudaFuncAttributeMaxDynamicSharedMemorySize, GEMM_SMEM);
    cudaFuncSetAttribute(adapter_o_kernel, cudaFuncAttributeMaxDynamicSharedMemorySize, GEMM_SMEM);
    cudaFuncSetAttribute(gemm_kernel<2, 1024, 1024>, cudaFuncAttributeMaxDynamicSharedMemorySize, GEMM_SMEM);
    cudaFuncSetAttribute(gemm_kernel<1, 1024, 4096>, cudaFuncAttributeMaxDynamicSharedMemorySize, GEMM_SMEM);
    cudaFuncSetAttribute(gemm_kernel<2, 4096, 1024>, cudaFuncAttributeMaxDynamicSharedMemorySize, GEMM_SMEM);
    cudaFuncSetAttribute(flash_mma_kernel, cudaFuncAttributeMaxDynamicSharedMemorySize, FLASH_SMEM);

    // 0) RoPE tables
    rope_table_kernel<<<Tq, 32>>>(p_rcos, p_rsin);

    // 1) AdaLN modulation
    mod_kernel<<<dim3(6 * Dm / 8, NB), 256>>>(cond, adaln_w, adaln_b, p_mod);

    // 2) pre-LN + modulate
    ln_mod_kernel<<<MR, 256>>>(x, ln_pre_w, ln_pre_b, p_mod, 0, Dm, p_xnorm);

    // 3) K/V (4 sources) + Q + adapter hidden, one batched launch
    kvq_kernel<<<dim3(8, 16, 12), 256, GEMM_SMEM>>>(
        p_xnorm, bev, vl, reas, k_w, k_b, v_w, v_b, q_proj_w, q_proj_b,
        qa_w, qa_b, p_kcat, p_vcat, p_q0, p_hidden);

    // 4) adapter out (batched over 3)
    adapter_o_kernel<<<dim3(8, 16, 3), 256, GEMM_SMEM>>>(p_hidden, qa_out_w, qa_out_b, p_qad);

    // 5) QK-norm + RoPE (single merged launch)
    qkpost_all_kernel<<<4 * MR + NB * KTOT, 256>>>(
        p_q0, p_qad, p_kcat, qn_w, kn_w, p_rcos, p_rsin);

    // 6) flash attention (tf32 mma, 128-q CTAs, cp.async double-buffered K/V)
    flash_mma_kernel<<<dim3(Tq / 128, NH, NB), 256, FLASH_SMEM>>>(
        p_q0, p_qad, p_qad + (size_t)MR * Dm, p_qad + (size_t)2 * MR * Dm,
        p_kcat, p_vcat, temps, sbias, gating, p_attn);

    // 7) o-proj + residual + gate_attn
    gemm_kernel<2, 1024, 1024><<<dim3(8, 16), 256, GEMM_SMEM>>>(
        p_attn, o_w, o_b, p_xa, x, p_mod, 2 * Dm);

    // 8) FFN
    ln_mod_kernel<<<MR, 256>>>(p_xa, ffn_ln_w, ffn_ln_b, p_mod, 3 * Dm, 4 * Dm, p_hln);
    gemm_kernel<1, 1024, 4096><<<dim3(32, 16), 256, GEMM_SMEM>>>(
        p_hln, ffn_w1, ffn_b1, p_hff, nullptr, nullptr, 0);
    gemm_kernel<2, 4096, 1024><<<dim3(8, 16), 256, GEMM_SMEM>>>(
        p_hff, ffn_w2, ffn_b2, out, p_xa, p_mod, 5 * Dm);
}

// round 14
// speedup vs baseline: 1.5141x; 1.5141x over previous
#include <cuda_runtime.h>
#include <math.h>
#include <stdint.h>

// ---------------- problem constants ----------------
#define Dm   1024
#define Tq   512
#define NB   4
#define NH   16
#define HDm  64
#define KTOT 1792
#define MR   2048        // NB*Tq rows
#define DFF  4096

// ---------------- scratch (device globals; no allocation) ----------------
__device__ float g_mod[NB * 6 * Dm];
__device__ float g_xnorm[MR * Dm];
__device__ float g_q0[MR * Dm];
__device__ float g_qad[3 * MR * Dm];
__device__ float g_hidden[3 * MR * 256];
__device__ float g_kcat[NB * KTOT * Dm];
__device__ float g_vcat[NB * KTOT * Dm];
__device__ float g_attnout[MR * Dm];
__device__ float g_xa[MR * Dm];
__device__ float g_hln[MR * Dm];
__device__ float g_hff[MR * DFF];
__device__ float g_rcos[Tq * 32];
__device__ float g_rsin[Tq * 32];

// ---------------- helpers ----------------
__device__ __forceinline__ void mma8(float* c, const uint32_t* a, const uint32_t* b) {
    asm volatile(
        "mma.sync.aligned.m16n8k8.row.col.f32.tf32.tf32.f32 "
        "{%0,%1,%2,%3},{%4,%5,%6,%7},{%8,%9},{%0,%1,%2,%3};\n"
        : "+f"(c[0]), "+f"(c[1]), "+f"(c[2]), "+f"(c[3])
        : "r"(a[0]), "r"(a[1]), "r"(a[2]), "r"(a[3]), "r"(b[0]), "r"(b[1]));
}

__device__ __forceinline__ void cpa16(uint32_t dst, const void* src) {
    asm volatile("cp.async.cg.shared.global [%0], [%1], 16;\n" :: "r"(dst), "l"(src));
}
#define CP_COMMIT() asm volatile("cp.async.commit_group;\n" ::)
#define CP_WAIT1()  asm volatile("cp.async.wait_group 1;\n" ::: "memory")
#define CP_WAIT0()  asm volatile("cp.async.wait_group 0;\n" ::: "memory")

// ================== tf32 GEMM core: C = A @ W^T + bias (+ epilogue) ==========
// 3-stage cp.async pipeline. Shared layout [m][k], row stride 20 floats:
// fragment-load banks (20g mod 32) + tc fill all 32 banks -> conflict-free.
// tf32 by HW truncation (no cvt). (Round-8 proven core, unchanged.)
#define GRS   20
#define GSTG  (128 * GRS)
#define GEMM_SMEM (2 * 3 * GSTG * 4)

template<int EPI, int Kc, int Nc>
__device__ __forceinline__ void gemm_core(
    const float* __restrict__ A, const float* __restrict__ W,
    const float* __restrict__ bias, float* __restrict__ C,
    int Lb, int outBatchRows, int outRowOff,
    const float* __restrict__ res, const float* __restrict__ mod, int gateOff,
    float* sm)
{
    float* As = sm;
    float* Bs = sm + 3 * GSTG;

    int tid  = threadIdx.x;
    int wid  = tid >> 5;
    int lane = tid & 31;
    int g  = lane >> 2;      // 0..7
    int tc = lane & 3;       // 0..3
    int warpM = (wid & 1) * 64;
    int warpN = (wid >> 1) * 32;

    int row0 = blockIdx.y * 128;
    int col0 = blockIdx.x * 128;

    int ldRow = tid >> 1;          // 0..127
    int ldCol = (tid & 1) * 8;     // 0 or 8
    const float* Ag = A + (size_t)(row0 + ldRow) * Kc + ldCol;
    const float* Wg = W + (size_t)(col0 + ldRow) * Kc + ldCol;
    uint32_t sAd = (uint32_t)__cvta_generic_to_shared(As + ldRow * GRS + ldCol);
    uint32_t sBd = (uint32_t)__cvta_generic_to_shared(Bs + ldRow * GRS + ldCol);

    const int NIT = Kc >> 4;

    float acc[4][4][4];
    #pragma unroll
    for (int mi = 0; mi < 4; mi++)
        #pragma unroll
        for (int ni = 0; ni < 4; ni++)
            #pragma unroll
            for (int e = 0; e < 4; e++) acc[mi][ni][e] = 0.f;

    auto issue = [&](int it) {
        uint32_t off = (uint32_t)(it % 3) * (GSTG * 4);
        const float* a = Ag + it * 16;
        const float* w = Wg + it * 16;
        cpa16(sAd + off, a);
        cpa16(sAd + off + 16, a + 4);
        cpa16(sBd + off, w);
        cpa16(sBd + off + 16, w + 4);
    };
    issue(0); CP_COMMIT();
    issue(1); CP_COMMIT();

    #pragma unroll 1
    for (int it = 0; it < NIT; it++) {
        CP_WAIT1();
        __syncthreads();
        if (it + 2 < NIT) issue(it + 2);
        CP_COMMIT();

        const float* Ast = As + (it % 3) * GSTG;
        const float* Bst = Bs + (it % 3) * GSTG;
        #pragma unroll
        for (int kb = 0; kb < 16; kb += 8) {
            uint32_t af[4][4];
            #pragma unroll
            for (int mi = 0; mi < 4; mi++) {
                int r = warpM + mi * 16 + g;
                af[mi][0] = __float_as_uint(Ast[r * GRS + kb + tc]);
                af[mi][1] = __float_as_uint(Ast[(r + 8) * GRS + kb + tc]);
                af[mi][2] = __float_as_uint(Ast[r * GRS + kb + tc + 4]);
                af[mi][3] = __float_as_uint(Ast[(r + 8) * GRS + kb + tc + 4]);
            }
            uint32_t bf_[4][2];
            #pragma unroll
            for (int ni = 0; ni < 4; ni++) {
                int cN = warpN + ni * 8 + g;
                bf_[ni][0] = __float_as_uint(Bst[cN * GRS + kb + tc]);
                bf_[ni][1] = __float_as_uint(Bst[cN * GRS + kb + tc + 4]);
            }
            #pragma unroll
            for (int mi = 0; mi < 4; mi++)
                #pragma unroll
                for (int ni = 0; ni < 4; ni++)
                    mma8(acc[mi][ni], af[mi], bf_[ni]);
        }
    }

    // epilogue
    #pragma unroll
    for (int mi = 0; mi < 4; mi++) {
        #pragma unroll
        for (int ib = 0; ib < 2; ib++) {
            int m = row0 + warpM + mi * 16 + g + ib * 8;
            int orow = (m / Lb) * outBatchRows + outRowOff + (m % Lb);
            const float* resr = (EPI == 2) ? res + (size_t)m * Nc : nullptr;
            const float* gr   = (EPI == 2) ? mod + (m / Tq) * (6 * Dm) + gateOff : nullptr;
            #pragma unroll
            for (int ni = 0; ni < 4; ni++) {
                int n = col0 + warpN + ni * 8 + tc * 2;
                float v0 = acc[mi][ni][ib * 2 + 0] + bias[n];
                float v1 = acc[mi][ni][ib * 2 + 1] + bias[n + 1];
                if (EPI == 1) {
                    v0 = 0.5f * v0 * (1.f + erff(v0 * 0.70710678118654752f));
                    v1 = 0.5f * v1 * (1.f + erff(v1 * 0.70710678118654752f));
                }
                if (EPI == 2) {
                    v0 = resr[n] + gr[n] * v0;
                    v1 = resr[n + 1] + gr[n + 1] * v1;
                }
                float2 o2 = {v0, v1};
                *(float2*)&C[(size_t)orow * Nc + n] = o2;
            }
        }
    }
}

// ---- batched K/V/Q + adapter_h: z=0..3 K, 4..7 V, 8 Q, 9..11 adapter_h ----
__global__ __launch_bounds__(256, 2) void kvq_kernel(
    const float* __restrict__ xnorm, const float* __restrict__ bev,
    const float* __restrict__ vl, const float* __restrict__ reas,
    const float* __restrict__ k_w, const float* __restrict__ k_b,
    const float* __restrict__ v_w, const float* __restrict__ v_b,
    const float* __restrict__ qw, const float* __restrict__ qb,
    const float* __restrict__ qa_w, const float* __restrict__ qa_b,
    float* __restrict__ kcat, float* __restrict__ vcat,
    float* __restrict__ q0, float* __restrict__ hidden)
{
    extern __shared__ float smg[];
    int z = blockIdx.z;
    if (z >= 9) {
        int a = z - 9;
        if (blockIdx.x >= 2) return;
        gemm_core<0, 1024, 256>(xnorm, qa_w + (size_t)a * 256 * Dm, qa_b + a * 256,
                                hidden + (size_t)a * MR * 256,
                                1 << 30, 0, 0, nullptr, nullptr, 0, smg);
        return;
    }
    const float* A; const float* W; const float* bias; float* C;
    int Lb, oBR, oRO;
    if (z < 8) {
        int src = z & 3;
        if (src == 3 && blockIdx.y >= 8) return;
        A = (src == 0) ? xnorm : (src == 1) ? bev : (src == 2) ? vl : reas;
        bool isV = z >= 4;
        W    = (isV ? v_w : k_w) + (size_t)src * Dm * Dm;
        bias = (isV ? v_b : k_b) + src * Dm;
        C    = isV ? vcat : kcat;
        Lb = (src == 3) ? 256 : 512;
        oBR = KTOT; oRO = src * 512;
    } else {
        A = xnorm; W = qw; bias = qb; C = q0;
        Lb = 1 << 30; oBR = 0; oRO = 0;
    }
    gemm_core<0, 1024, 1024>(A, W, bias, C, Lb, oBR, oRO, nullptr, nullptr, 0, smg);
}

// ---- batched adapter out: z = 0..2 ----
__global__ __launch_bounds__(256, 2) void adapter_o_kernel(
    const float* __restrict__ hidden, const float* __restrict__ qa_out_w,
    const float* __restrict__ qa_out_b, float* __restrict__ qad)
{
    extern __shared__ float smg[];
    int z = blockIdx.z;
    gemm_core<0, 256, 1024>(hidden + (size_t)z * MR * 256, qa_out_w, qa_out_b,
                            qad + (size_t)z * MR * Dm,
                            1 << 30, 0, 0, nullptr, nullptr, 0, smg);
}

// ---- generic (identity remap) GEMM ----
template<int EPI, int Kc, int Nc>
__global__ __launch_bounds__(256, 2) void gemm_kernel(
    const float* __restrict__ A, const float* __restrict__ W,
    const float* __restrict__ bias, float* __restrict__ C,
    const float* __restrict__ res, const float* __restrict__ mod, int gateOff)
{
    extern __shared__ float smg[];
    gemm_core<EPI, Kc, Nc>(A, W, bias, C, 1 << 30, 0, 0, res, mod, gateOff, smg);
}

// ---------------- mod = silu(cond) @ adaln_w^T + adaln_b ----------------
__global__ __launch_bounds__(256) void mod_kernel(const float* __restrict__ cond,
                                                  const float* __restrict__ W,
                                                  const float* __restrict__ bb,
                                                  float* __restrict__ mod)
{
    int b = blockIdx.y;
    __shared__ float sc[Dm];
    for (int i = threadIdx.x; i < Dm; i += 256) {
        float c = cond[b * Dm + i];
        sc[i] = c / (1.f + expf(-c));
    }
    __syncthreads();
    int w = threadIdx.x >> 5, lane = threadIdx.x & 31;
    int n = blockIdx.x * 8 + w;
    const float* wr = W + (size_t)n * Dm;
    float acc = 0.f;
    for (int k = lane; k < Dm; k += 32) acc += sc[k] * wr[k];
    #pragma unroll
    for (int o = 16; o; o >>= 1) acc += __shfl_xor_sync(~0u, acc, o);
    if (lane == 0) mod[b * 6 * Dm + n] = acc + bb[n];
}

// ---------------- LayerNorm + AdaLN modulate ----------------
__global__ __launch_bounds__(256) void ln_mod_kernel(const float* __restrict__ x,
                                                     const float* __restrict__ w,
                                                     const float* __restrict__ bvec,
                                                     const float* __restrict__ mod,
                                                     int shiftOff, int scaleOff,
                                                     float* __restrict__ out)
{
    int row = blockIdx.x;
    int tid = threadIdx.x;
    float4 v = ((const float4*)(x + (size_t)row * Dm))[tid];
    float s = v.x + v.y + v.z + v.w;
    float q = v.x * v.x + v.y * v.y + v.z * v.z + v.w * v.w;
    __shared__ float rs[8], rq[8];
    #pragma unroll
    for (int o = 16; o; o >>= 1) {
        s += __shfl_xor_sync(~0u, s, o);
        q += __shfl_xor_sync(~0u, q, o);
    }
    if ((tid & 31) == 0) { rs[tid >> 5] = s; rq[tid >> 5] = q; }
    __syncthreads();
    float sum = 0.f, sq = 0.f;
    #pragma unroll
    for (int i = 0; i < 8; i++) { sum += rs[i]; sq += rq[i]; }
    float mean = sum * (1.f / Dm);
    float var  = sq * (1.f / Dm) - mean * mean;
    float inv  = rsqrtf(var + 1e-5f);
    const float* ms = mod + (row / Tq) * (6 * Dm);
    int d = tid * 4;
    float in[4] = {v.x, v.y, v.z, v.w};
    float4 ov;
    float* po = (float*)&ov;
    #pragma unroll
    for (int e = 0; e < 4; e++) {
        float xn = (in[e] - mean) * inv * w[d + e] + bvec[d + e];
        po[e] = xn * (1.f + ms[scaleOff + d + e]) + ms[shiftOff + d + e];
    }
    ((float4*)(out + (size_t)row * Dm))[tid] = ov;
}

// ---------------- RoPE table ----------------
__global__ void rope_table_kernel(float* __restrict__ c, float* __restrict__ s)
{
    int pos = blockIdx.x, j = threadIdx.x;
    float ang = (float)pos * expf(-(float)j * (9.2103403719761836f / 32.f));
    float sn, cs;
    sincosf(ang, &sn, &cs);
    c[pos * 32 + j] = cs;
    s[pos * 32 + j] = sn;
}

// -------- QK post, merged: q0 rows [0,MR), qad [MR,4MR), kcat [4MR,4MR+NB*KTOT)
__global__ __launch_bounds__(256) void qkpost_all_kernel(
    float* __restrict__ q0, float* __restrict__ qad, float* __restrict__ kcat,
    const float* __restrict__ qn_w, const float* __restrict__ kn_w,
    const float* __restrict__ rc, const float* __restrict__ rs)
{
    int row = blockIdx.x, tid = threadIdx.x;
    float* rp;
    const float* w;
    int pos;
    if (row < MR) {
        rp = q0 + (size_t)row * Dm; w = qn_w; pos = row & (Tq - 1);
    } else if (row < 4 * MR) {
        rp = qad + (size_t)(row - MR) * Dm; w = qn_w; pos = -1;
    } else {
        int r = row - 4 * MR;
        rp = kcat + (size_t)r * Dm; w = kn_w;
        int rr = r % KTOT;
        pos = (rr < 512) ? rr : (rr < 1024) ? rr - 512 : (rr < 1536) ? rr - 1024 : rr - 1536;
    }
    float4 v = ((float4*)rp)[tid];
    float ss = v.x * v.x + v.y * v.y + v.z * v.z + v.w * v.w;
    ss += __shfl_xor_sync(~0u, ss, 1, 16);
    ss += __shfl_xor_sync(~0u, ss, 2, 16);
    ss += __shfl_xor_sync(~0u, ss, 4, 16);
    ss += __shfl_xor_sync(~0u, ss, 8, 16);
    float inv = rsqrtf(ss * (1.f / 64.f) + 1e-6f);
    int dl = (tid & 15) * 4;
    float nv[4] = {v.x * inv * w[dl], v.y * inv * w[dl + 1],
                   v.z * inv * w[dl + 2], v.w * inv * w[dl + 3]};
    if (pos >= 0) {
        float pv[4];
        #pragma unroll
        for (int e = 0; e < 4; e++) pv[e] = __shfl_xor_sync(~0u, nv[e], 8, 16);
        bool firstHalf = dl < 32;
        int jb = dl & 31;
        float4 c4 = *(const float4*)&rc[pos * 32 + jb];
        float4 s4 = *(const float4*)&rs[pos * 32 + jb];
        float cse[4] = {c4.x, c4.y, c4.z, c4.w};
        float sne[4] = {s4.x, s4.y, s4.z, s4.w};
        #pragma unroll
        for (int e = 0; e < 4; e++) {
            nv[e] = firstHalf ? (nv[e] * cse[e] - pv[e] * sne[e])
                              : (nv[e] * cse[e] + pv[e] * sne[e]);
        }
    }
    float4 o = {nv[0], nv[1], nv[2], nv[3]};
    ((float4*)rp)[tid] = o;
}

// ============ Flash attention, tf32 mma + cp.async double-buffered K/V ======
// 128 queries x 1 head per CTA (256 threads, 8 warps, 16q x 64kk warp tile).
// K/V tiles contiguous across segments -> single prefetch stream. Layouts:
// Qs/Ks stride 84, Vs stride 72 (bank-conflict-free fragment loads).
#define QKS 84
#define VS  72
#define KVSTG (64 * QKS + 64 * VS)
#define FLASH_SMEM ((128 * QKS + 2 * KVSTG) * 4)

__global__ __launch_bounds__(256) void flash_mma_kernel(
    const float* __restrict__ q0p, const float* __restrict__ q1p,
    const float* __restrict__ q2p, const float* __restrict__ q3p,
    const float* __restrict__ kcat, const float* __restrict__ vcat,
    const float* __restrict__ temps, const float* __restrict__ sbias,
    const float* __restrict__ gating, float* __restrict__ outp)
{
    extern __shared__ float sm[];
    float* Qs  = sm;                    // [128][84]
    float* KV0 = sm + 128 * QKS;        // stage 0: K [64][84] + V [64][72]
    float* KV1 = KV0 + KVSTG;           // stage 1

    int tid = threadIdx.x;
    int wid = tid >> 5, lane = tid & 31;
    int g = lane >> 2, tc = lane & 3;
    int q0w = wid * 16;                 // 0..112
    int h = blockIdx.y, b = blockIdx.z;
    int qbase = b * Tq + blockIdx.x * 128;

    const float* qp[4] = {q0p, q1p, q2p, q3p};
    float rg = tanhf(gating[0]);

    float m0 = -1e30f, m1 = -1e30f, l0 = 0.f, l1 = 0.f;
    float Oacc[8][4];
    #pragma unroll
    for (int dt = 0; dt < 8; dt++)
        #pragma unroll
        for (int e = 0; e < 4; e++) Oacc[dt][e] = 0.f;

    // KV staging: 256 threads cover 64 rows x 64 d; 16 floats each
    int sr  = tid & 63;
    int scb = (tid >> 6) * 16;          // 0,16,32,48
    uint32_t kd0 = (uint32_t)__cvta_generic_to_shared(KV0 + sr * QKS + scb);
    uint32_t vd0 = (uint32_t)__cvta_generic_to_shared(KV0 + 64 * QKS + sr * VS + scb);
    const float* srcK0 = kcat + (size_t)(b * KTOT + sr) * Dm + h * HDm + scb;
    const float* srcV0 = vcat + (size_t)(b * KTOT + sr) * Dm + h * HDm + scb;

    // Q staging: 256 threads cover 128 rows x 64 d; 32 floats each
    int qr  = tid >> 1;
    int qcb = (tid & 1) * 32;

    int srcA = (lane & ~3) | (tc >> 1);
    int srcB = srcA + 2;
    bool odd = tc & 1;

    auto issue_kv = [&](int t) {
        uint32_t off = (uint32_t)(t & 1) * (KVSTG * 4);
        const float* sk = srcK0 + (size_t)t * 64 * Dm;
        const float* sv = srcV0 + (size_t)t * 64 * Dm;
        #pragma unroll
        for (int j = 0; j < 4; j++) {
            cpa16(kd0 + off + j * 16, sk + j * 4);
            cpa16(vd0 + off + j * 16, sv + j * 4);
        }
    };

    issue_kv(0); CP_COMMIT();
    int t = 0;

    for (int seg = 0; seg < 4; seg++) {
        float tt = temps[seg];
        float sp = tt > 20.f ? tt : log1pf(expf(tt));
        float scale = 0.125f * (1.f + sp);
        float sb = sbias[seg];
        if (seg == 3) { scale *= rg; sb *= rg; }

        // stage Q variant (natural [q][d]); Qs untouched by kv pipeline
        __syncthreads();
        {
            const float* src = qp[seg] + (size_t)(qbase + qr) * Dm + h * HDm + qcb;
            float* qd = &Qs[qr * QKS + qcb];
            #pragma unroll
            for (int j4 = 0; j4 < 8; j4++)
                *(float4*)(qd + j4 * 4) = ((const float4*)src)[j4];
        }
        __syncthreads();
        // preload Q fragments (reused for all k-tiles of this segment)
        uint32_t qf[8][4];
        #pragma unroll
        for (int c = 0; c < 8; c++) {
            qf[c][0] = __float_as_uint(Qs[(q0w + g) * QKS + c * 8 + tc]);
            qf[c][1] = __float_as_uint(Qs[(q0w + g + 8) * QKS + c * 8 + tc]);
            qf[c][2] = __float_as_uint(Qs[(q0w + g) * QKS + c * 8 + tc + 4]);
            qf[c][3] = __float_as_uint(Qs[(q0w + g + 8) * QKS + c * 8 + tc + 4]);
        }

        int nt = (seg == 3) ? 4 : 8;
        for (int kt = 0; kt < nt; kt++, t++) {
            CP_WAIT0();
            __syncthreads();
            if (t + 1 < 28) issue_kv(t + 1);
            CP_COMMIT();

            const float* Ks = (t & 1) ? KV1 : KV0;
            const float* Vs = Ks + 64 * QKS;

            // ---- S = Q K^T (16q x 64kk per warp) ----
            float S[8][4];
            #pragma unroll
            for (int ni = 0; ni < 8; ni++)
                #pragma unroll
                for (int e = 0; e < 4; e++) S[ni][e] = 0.f;
            #pragma unroll
            for (int c = 0; c < 8; c++) {
                #pragma unroll
                for (int ni = 0; ni < 8; ni++) {
                    uint32_t bf[2];
                    bf[0] = __float_as_uint(Ks[(ni * 8 + g) * QKS + c * 8 + tc]);
                    bf[1] = __float_as_uint(Ks[(ni * 8 + g) * QKS + c * 8 + tc + 4]);
                    mma8(S[ni], qf[c], bf);
                }
            }

            // ---- online softmax (rows g, g+8 of warp tile) ----
            float r0 = -1e30f, r1 = -1e30f;
            #pragma unroll
            for (int ni = 0; ni < 8; ni++) {
                S[ni][0] = fmaf(S[ni][0], scale, sb);
                S[ni][1] = fmaf(S[ni][1], scale, sb);
                S[ni][2] = fmaf(S[ni][2], scale, sb);
                S[ni][3] = fmaf(S[ni][3], scale, sb);
                r0 = fmaxf(r0, fmaxf(S[ni][0], S[ni][1]));
                r1 = fmaxf(r1, fmaxf(S[ni][2], S[ni][3]));
            }
            r0 = fmaxf(r0, __shfl_xor_sync(~0u, r0, 1));
            r0 = fmaxf(r0, __shfl_xor_sync(~0u, r0, 2));
            r1 = fmaxf(r1, __shfl_xor_sync(~0u, r1, 1));
            r1 = fmaxf(r1, __shfl_xor_sync(~0u, r1, 2));
            float mn0 = fmaxf(m0, r0), mn1 = fmaxf(m1, r1);
            float f0 = __expf(m0 - mn0), f1 = __expf(m1 - mn1);
            float s0 = 0.f, s1 = 0.f;
            #pragma unroll
            for (int ni = 0; ni < 8; ni++) {
                S[ni][0] = __expf(S[ni][0] - mn0);
                S[ni][1] = __expf(S[ni][1] - mn0);
                S[ni][2] = __expf(S[ni][2] - mn1);
                S[ni][3] = __expf(S[ni][3] - mn1);
                s0 += S[ni][0] + S[ni][1];
                s1 += S[ni][2] + S[ni][3];
            }
            s0 += __shfl_xor_sync(~0u, s0, 1);
            s0 += __shfl_xor_sync(~0u, s0, 2);
            s1 += __shfl_xor_sync(~0u, s1, 1);
            s1 += __shfl_xor_sync(~0u, s1, 2);
            l0 = l0 * f0 + s0;
            l1 = l1 * f1 + s1;
            m0 = mn0; m1 = mn1;
            #pragma unroll
            for (int dt = 0; dt < 8; dt++) {
                Oacc[dt][0] *= f0; Oacc[dt][1] *= f0;
                Oacc[dt][2] *= f1; Oacc[dt][3] *= f1;
            }

            // ---- O += P V  (P from registers via lane transpose) ----
            #pragma unroll
            for (int ni = 0; ni < 8; ni++) {
                float p0 = S[ni][0], p1 = S[ni][1];
                float p2 = S[ni][2], p3 = S[ni][3];
                float x0 = __shfl_sync(~0u, p0, srcA), y0 = __shfl_sync(~0u, p1, srcA);
                float x2 = __shfl_sync(~0u, p0, srcB), y2 = __shfl_sync(~0u, p1, srcB);
                float x1 = __shfl_sync(~0u, p2, srcA), y1 = __shfl_sync(~0u, p3, srcA);
                float x3 = __shfl_sync(~0u, p2, srcB), y3 = __shfl_sync(~0u, p3, srcB);
                uint32_t ap[4];
                ap[0] = __float_as_uint(odd ? y0 : x0);
                ap[1] = __float_as_uint(odd ? y1 : x1);
                ap[2] = __float_as_uint(odd ? y2 : x2);
                ap[3] = __float_as_uint(odd ? y3 : x3);
                #pragma unroll
                for (int dt = 0; dt < 8; dt++) {
                    uint32_t bv[2];
                    bv[0] = __float_as_uint(Vs[(ni * 8 + tc) * VS + dt * 8 + g]);
                    bv[1] = __float_as_uint(Vs[(ni * 8 + tc + 4) * VS + dt * 8 + g]);
                    mma8(Oacc[dt], ap, bv);
                }
            }
        }
    }

    float i0 = 1.f / l0, i1 = 1.f / l1;
    int qg0 = qbase + q0w + g, qg1 = qg0 + 8;
    #pragma unroll
    for (int dt = 0; dt < 8; dt++) {
        int dcol = h * HDm + dt * 8 + tc * 2;
        float2 o0 = {Oacc[dt][0] * i0, Oacc[dt][1] * i0};
        float2 o1 = {Oacc[dt][2] * i1, Oacc[dt][3] * i1};
        *(float2*)&outp[(size_t)qg0 * Dm + dcol] = o0;
        *(float2*)&outp[(size_t)qg1 * Dm + dcol] = o1;
    }
}

// ---------------- launch ----------------
static float* symaddr(const void* s) {
    void* p = nullptr;
    cudaGetSymbolAddress(&p, s);
    return (float*)p;
}

extern "C" void kernel_launch(void* const* d_in, const int* in_sizes, int n_in,
                              void* d_out, int out_size)
{
    const float* x        = (const float*)d_in[0];
    const float* bev      = (const float*)d_in[1];
    const float* vl       = (const float*)d_in[2];
    const float* reas     = (const float*)d_in[3];
    const float* cond     = (const float*)d_in[4];
    const float* ln_pre_w = (const float*)d_in[5];
    const float* ln_pre_b = (const float*)d_in[6];
    const float* adaln_w  = (const float*)d_in[7];
    const float* adaln_b  = (const float*)d_in[8];
    const float* q_proj_w = (const float*)d_in[9];
    const float* q_proj_b = (const float*)d_in[10];
    const float* qa_w     = (const float*)d_in[11];
    const float* qa_b     = (const float*)d_in[12];
    const float* qa_out_w = (const float*)d_in[13];
    const float* qa_out_b = (const float*)d_in[14];
    const float* k_w      = (const float*)d_in[15];
    const float* k_b      = (const float*)d_in[16];
    const float* v_w      = (const float*)d_in[17];
    const float* v_b      = (const float*)d_in[18];
    const float* o_w      = (const float*)d_in[19];
    const float* o_b      = (const float*)d_in[20];
    const float* qn_w     = (const float*)d_in[21];
    const float* kn_w     = (const float*)d_in[22];
    const float* gating   = (const float*)d_in[23];
    const float* temps    = (const float*)d_in[24];
    const float* sbias    = (const float*)d_in[25];
    const float* ffn_ln_w = (const float*)d_in[26];
    const float* ffn_ln_b = (const float*)d_in[27];
    const float* ffn_w1   = (const float*)d_in[28];
    const float* ffn_b1   = (const float*)d_in[29];
    const float* ffn_w2   = (const float*)d_in[30];
    const float* ffn_b2   = (const float*)d_in[31];
    float* out = (float*)d_out;

    float* p_mod    = symaddr(g_mod);
    float* p_xnorm  = symaddr(g_xnorm);
    float* p_q0     = symaddr(g_q0);
    float* p_qad    = symaddr(g_qad);
    float* p_hidden = symaddr(g_hidden);
    float* p_kcat   = symaddr(g_kcat);
    float* p_vcat   = symaddr(g_vcat);
    float* p_attn   = symaddr(g_attnout);
    float* p_xa     = symaddr(g_xa);
    float* p_hln    = symaddr(g_hln);
    float* p_hff    = symaddr(g_hff);
    float* p_rcos   = symaddr(g_rcos);
    float* p_rsin   = symaddr(g_rsin);

    cudaFuncSetAttribute(kvq_kernel, cudaFuncAttributeMaxDynamicSharedMemorySize, GEMM_SMEM);
    cudaFuncSetAttribute(adapter_o_kernel, cudaFuncAttributeMaxDynamicSharedMemorySize, GEMM_SMEM);
    cudaFuncSetAttribute(gemm_kernel<2, 1024, 1024>, cudaFuncAttributeMaxDynamicSharedMemorySize, GEMM_SMEM);
    cudaFuncSetAttribute(gemm_kernel<1, 1024, 4096>, cudaFuncAttributeMaxDynamicSharedMemorySize, GEMM_SMEM);
    cudaFuncSetAttribute(gemm_kernel<2, 4096, 1024>, cudaFuncAttributeMaxDynamicSharedMemorySize, GEMM_SMEM);
    cudaFuncSetAttribute(flash_mma_kernel, cudaFuncAttributeMaxDynamicSharedMemorySize, FLASH_SMEM);

    // 0) RoPE tables
    rope_table_kernel<<<Tq, 32>>>(p_rcos, p_rsin);

    // 1) AdaLN modulation
    mod_kernel<<<dim3(6 * Dm / 8, NB), 256>>>(cond, adaln_w, adaln_b, p_mod);

    // 2) pre-LN + modulate
    ln_mod_kernel<<<MR, 256>>>(x, ln_pre_w, ln_pre_b, p_mod, 0, Dm, p_xnorm);

    // 3) K/V (4 sources) + Q + adapter hidden, one batched launch
    kvq_kernel<<<dim3(8, 16, 12), 256, GEMM_SMEM>>>(
        p_xnorm, bev, vl, reas, k_w, k_b, v_w, v_b, q_proj_w, q_proj_b,
        qa_w, qa_b, p_kcat, p_vcat, p_q0, p_hidden);

    // 4) adapter out (batched over 3)
    adapter_o_kernel<<<dim3(8, 16, 3), 256, GEMM_SMEM>>>(p_hidden, qa_out_w, qa_out_b, p_qad);

    // 5) QK-norm + RoPE (single merged launch)
    qkpost_all_kernel<<<4 * MR + NB * KTOT, 256>>>(
        p_q0, p_qad, p_kcat, qn_w, kn_w, p_rcos, p_rsin);

    // 6) flash attention (tf32 mma, 128-q CTAs, cp.async double-buffered K/V)
    flash_mma_kernel<<<dim3(Tq / 128, NH, NB), 256, FLASH_SMEM>>>(
        p_q0, p_qad, p_qad + (size_t)MR * Dm, p_qad + (size_t)2 * MR * Dm,
        p_kcat, p_vcat, temps, sbias, gating, p_attn);

    // 7) o-proj + residual + gate_attn
    gemm_kernel<2, 1024, 1024><<<dim3(8, 16), 256, GEMM_SMEM>>>(
        p_attn, o_w, o_b, p_xa, x, p_mod, 2 * Dm);

    // 8) FFN
    ln_mod_kernel<<<MR, 256>>>(p_xa, ffn_ln_w, ffn_ln_b, p_mod, 3 * Dm, 4 * Dm, p_hln);
    gemm_kernel<1, 1024, 4096><<<dim3(32, 16), 256, GEMM_SMEM>>>(
        p_hln, ffn_w1, ffn_b1, p_hff, nullptr, nullptr, 0);
    gemm_kernel<2, 4096, 1024><<<dim3(8, 16), 256, GEMM_SMEM>>>(
        p_hff, ffn_w2, ffn_b2, out, p_xa, p_mod, 5 * Dm);
}

// round 16
// speedup vs baseline: 1.5373x; 1.0153x over previous
#include <cuda_runtime.h>
#include <math.h>
#include <stdint.h>

// ---------------- problem constants ----------------
#define Dm   1024
#define Tq   512
#define NB   4
#define NH   16
#define HDm  64
#define KTOT 1792
#define MR   2048        // NB*Tq rows
#define DFF  4096

// ---------------- scratch (device globals; no allocation) ----------------
__device__ float g_mod[NB * 6 * Dm];
__device__ float g_xnorm[MR * Dm];
__device__ float g_q0[MR * Dm];
__device__ float g_qad[3 * MR * Dm];
__device__ float g_hidden[3 * MR * 256];
__device__ float g_kcat[NB * KTOT * Dm];
__device__ float g_vcat[NB * KTOT * Dm];
__device__ float g_attnout[MR * Dm];
__device__ float g_xa[MR * Dm];
__device__ float g_hln[MR * Dm];
__device__ float g_hff[MR * DFF];
__device__ float g_rcos[Tq * 32];
__device__ float g_rsin[Tq * 32];

// ---------------- helpers ----------------
__device__ __forceinline__ void mma8(float* c, const uint32_t* a, const uint32_t* b) {
    asm volatile(
        "mma.sync.aligned.m16n8k8.row.col.f32.tf32.tf32.f32 "
        "{%0,%1,%2,%3},{%4,%5,%6,%7},{%8,%9},{%0,%1,%2,%3};\n"
        : "+f"(c[0]), "+f"(c[1]), "+f"(c[2]), "+f"(c[3])
        : "r"(a[0]), "r"(a[1]), "r"(a[2]), "r"(a[3]), "r"(b[0]), "r"(b[1]));
}

__device__ __forceinline__ void cpa16(uint32_t dst, const void* src) {
    asm volatile("cp.async.cg.shared.global [%0], [%1], 16;\n" :: "r"(dst), "l"(src));
}
#define CP_COMMIT() asm volatile("cp.async.commit_group;\n" ::)
#define CP_WAIT1()  asm volatile("cp.async.wait_group 1;\n" ::: "memory")

// ================== tf32 GEMM core: C = A @ W^T + bias (+ epilogue) ==========
// 3-stage cp.async pipeline. Shared layout [m][k], row stride 20 floats:
// fragment-load banks (20g mod 32) + tc fill all 32 banks -> conflict-free.
// tf32 by HW truncation (no cvt). (Round-8 proven core, unchanged.)
#define GRS   20
#define GSTG  (128 * GRS)
#define GEMM_SMEM (2 * 3 * GSTG * 4)

template<int EPI, int Kc, int Nc>
__device__ __forceinline__ void gemm_core(
    const float* __restrict__ A, const float* __restrict__ W,
    const float* __restrict__ bias, float* __restrict__ C,
    int Lb, int outBatchRows, int outRowOff,
    const float* __restrict__ res, const float* __restrict__ mod, int gateOff,
    float* sm)
{
    float* As = sm;
    float* Bs = sm + 3 * GSTG;

    int tid  = threadIdx.x;
    int wid  = tid >> 5;
    int lane = tid & 31;
    int g  = lane >> 2;      // 0..7
    int tc = lane & 3;       // 0..3
    int warpM = (wid & 1) * 64;
    int warpN = (wid >> 1) * 32;

    int row0 = blockIdx.y * 128;
    int col0 = blockIdx.x * 128;

    int ldRow = tid >> 1;          // 0..127
    int ldCol = (tid & 1) * 8;     // 0 or 8
    const float* Ag = A + (size_t)(row0 + ldRow) * Kc + ldCol;
    const float* Wg = W + (size_t)(col0 + ldRow) * Kc + ldCol;
    uint32_t sAd = (uint32_t)__cvta_generic_to_shared(As + ldRow * GRS + ldCol);
    uint32_t sBd = (uint32_t)__cvta_generic_to_shared(Bs + ldRow * GRS + ldCol);

    const int NIT = Kc >> 4;

    float acc[4][4][4];
    #pragma unroll
    for (int mi = 0; mi < 4; mi++)
        #pragma unroll
        for (int ni = 0; ni < 4; ni++)
            #pragma unroll
            for (int e = 0; e < 4; e++) acc[mi][ni][e] = 0.f;

    auto issue = [&](int it) {
        uint32_t off = (uint32_t)(it % 3) * (GSTG * 4);
        const float* a = Ag + it * 16;
        const float* w = Wg + it * 16;
        cpa16(sAd + off, a);
        cpa16(sAd + off + 16, a + 4);
        cpa16(sBd + off, w);
        cpa16(sBd + off + 16, w + 4);
    };
    issue(0); CP_COMMIT();
    issue(1); CP_COMMIT();

    #pragma unroll 1
    for (int it = 0; it < NIT; it++) {
        CP_WAIT1();
        __syncthreads();
        if (it + 2 < NIT) issue(it + 2);
        CP_COMMIT();

        const float* Ast = As + (it % 3) * GSTG;
        const float* Bst = Bs + (it % 3) * GSTG;
        #pragma unroll
        for (int kb = 0; kb < 16; kb += 8) {
            uint32_t af[4][4];
            #pragma unroll
            for (int mi = 0; mi < 4; mi++) {
                int r = warpM + mi * 16 + g;
                af[mi][0] = __float_as_uint(Ast[r * GRS + kb + tc]);
                af[mi][1] = __float_as_uint(Ast[(r + 8) * GRS + kb + tc]);
                af[mi][2] = __float_as_uint(Ast[r * GRS + kb + tc + 4]);
                af[mi][3] = __float_as_uint(Ast[(r + 8) * GRS + kb + tc + 4]);
            }
            uint32_t bf_[4][2];
            #pragma unroll
            for (int ni = 0; ni < 4; ni++) {
                int cN = warpN + ni * 8 + g;
                bf_[ni][0] = __float_as_uint(Bst[cN * GRS + kb + tc]);
                bf_[ni][1] = __float_as_uint(Bst[cN * GRS + kb + tc + 4]);
            }
            #pragma unroll
            for (int mi = 0; mi < 4; mi++)
                #pragma unroll
                for (int ni = 0; ni < 4; ni++)
                    mma8(acc[mi][ni], af[mi], bf_[ni]);
        }
    }

    // epilogue
    #pragma unroll
    for (int mi = 0; mi < 4; mi++) {
        #pragma unroll
        for (int ib = 0; ib < 2; ib++) {
            int m = row0 + warpM + mi * 16 + g + ib * 8;
            int orow = (m / Lb) * outBatchRows + outRowOff + (m % Lb);
            const float* resr = (EPI == 2) ? res + (size_t)m * Nc : nullptr;
            const float* gr   = (EPI == 2) ? mod + (m / Tq) * (6 * Dm) + gateOff : nullptr;
            #pragma unroll
            for (int ni = 0; ni < 4; ni++) {
                int n = col0 + warpN + ni * 8 + tc * 2;
                float v0 = acc[mi][ni][ib * 2 + 0] + bias[n];
                float v1 = acc[mi][ni][ib * 2 + 1] + bias[n + 1];
                if (EPI == 1) {
                    v0 = 0.5f * v0 * (1.f + erff(v0 * 0.70710678118654752f));
                    v1 = 0.5f * v1 * (1.f + erff(v1 * 0.70710678118654752f));
                }
                if (EPI == 2) {
                    v0 = resr[n] + gr[n] * v0;
                    v1 = resr[n + 1] + gr[n + 1] * v1;
                }
                float2 o2 = {v0, v1};
                *(float2*)&C[(size_t)orow * Nc + n] = o2;
            }
        }
    }
}

// ---- batched K/V/Q + adapter_h: z=0..3 K, 4..7 V, 8 Q, 9..11 adapter_h ----
__global__ __launch_bounds__(256, 2) void kvq_kernel(
    const float* __restrict__ xnorm, const float* __restrict__ bev,
    const float* __restrict__ vl, const float* __restrict__ reas,
    const float* __restrict__ k_w, const float* __restrict__ k_b,
    const float* __restrict__ v_w, const float* __restrict__ v_b,
    const float* __restrict__ qw, const float* __restrict__ qb,
    const float* __restrict__ qa_w, const float* __restrict__ qa_b,
    float* __restrict__ kcat, float* __restrict__ vcat,
    float* __restrict__ q0, float* __restrict__ hidden)
{
    extern __shared__ float smg[];
    int z = blockIdx.z;
    if (z >= 9) {
        int a = z - 9;
        if (blockIdx.x >= 2) return;
        gemm_core<0, 1024, 256>(xnorm, qa_w + (size_t)a * 256 * Dm, qa_b + a * 256,
                                hidden + (size_t)a * MR * 256,
                                1 << 30, 0, 0, nullptr, nullptr, 0, smg);
        return;
    }
    const float* A; const float* W; const float* bias; float* C;
    int Lb, oBR, oRO;
    if (z < 8) {
        int src = z & 3;
        if (src == 3 && blockIdx.y >= 8) return;
        A = (src == 0) ? xnorm : (src == 1) ? bev : (src == 2) ? vl : reas;
        bool isV = z >= 4;
        W    = (isV ? v_w : k_w) + (size_t)src * Dm * Dm;
        bias = (isV ? v_b : k_b) + src * Dm;
        C    = isV ? vcat : kcat;
        Lb = (src == 3) ? 256 : 512;
        oBR = KTOT; oRO = src * 512;
    } else {
        A = xnorm; W = qw; bias = qb; C = q0;
        Lb = 1 << 30; oBR = 0; oRO = 0;
    }
    gemm_core<0, 1024, 1024>(A, W, bias, C, Lb, oBR, oRO, nullptr, nullptr, 0, smg);
}

// ---- batched adapter out: z = 0..2 ----
__global__ __launch_bounds__(256, 2) void adapter_o_kernel(
    const float* __restrict__ hidden, const float* __restrict__ qa_out_w,
    const float* __restrict__ qa_out_b, float* __restrict__ qad)
{
    extern __shared__ float smg[];
    int z = blockIdx.z;
    gemm_core<0, 256, 1024>(hidden + (size_t)z * MR * 256, qa_out_w, qa_out_b,
                            qad + (size_t)z * MR * Dm,
                            1 << 30, 0, 0, nullptr, nullptr, 0, smg);
}

// ---- generic (identity remap) GEMM ----
template<int EPI, int Kc, int Nc>
__global__ __launch_bounds__(256, 2) void gemm_kernel(
    const float* __restrict__ A, const float* __restrict__ W,
    const float* __restrict__ bias, float* __restrict__ C,
    const float* __restrict__ res, const float* __restrict__ mod, int gateOff)
{
    extern __shared__ float smg[];
    gemm_core<EPI, Kc, Nc>(A, W, bias, C, 1 << 30, 0, 0, res, mod, gateOff, smg);
}

// ---------------- mod = silu(cond) @ adaln_w^T + adaln_b ----------------
__global__ __launch_bounds__(256) void mod_kernel(const float* __restrict__ cond,
                                                  const float* __restrict__ W,
                                                  const float* __restrict__ bb,
                                                  float* __restrict__ mod)
{
    int b = blockIdx.y;
    __shared__ float sc[Dm];
    for (int i = threadIdx.x; i < Dm; i += 256) {
        float c = cond[b * Dm + i];
        sc[i] = c / (1.f + expf(-c));
    }
    __syncthreads();
    int w = threadIdx.x >> 5, lane = threadIdx.x & 31;
    int n = blockIdx.x * 8 + w;
    const float* wr = W + (size_t)n * Dm;
    float acc = 0.f;
    for (int k = lane; k < Dm; k += 32) acc += sc[k] * wr[k];
    #pragma unroll
    for (int o = 16; o; o >>= 1) acc += __shfl_xor_sync(~0u, acc, o);
    if (lane == 0) mod[b * 6 * Dm + n] = acc + bb[n];
}

// ---------------- LayerNorm + AdaLN modulate ----------------
__global__ __launch_bounds__(256) void ln_mod_kernel(const float* __restrict__ x,
                                                     const float* __restrict__ w,
                                                     const float* __restrict__ bvec,
                                                     const float* __restrict__ mod,
                                                     int shiftOff, int scaleOff,
                                                     float* __restrict__ out)
{
    int row = blockIdx.x;
    int tid = threadIdx.x;
    float4 v = ((const float4*)(x + (size_t)row * Dm))[tid];
    float s = v.x + v.y + v.z + v.w;
    float q = v.x * v.x + v.y * v.y + v.z * v.z + v.w * v.w;
    __shared__ float rs[8], rq[8];
    #pragma unroll
    for (int o = 16; o; o >>= 1) {
        s += __shfl_xor_sync(~0u, s, o);
        q += __shfl_xor_sync(~0u, q, o);
    }
    if ((tid & 31) == 0) { rs[tid >> 5] = s; rq[tid >> 5] = q; }
    __syncthreads();
    float sum = 0.f, sq = 0.f;
    #pragma unroll
    for (int i = 0; i < 8; i++) { sum += rs[i]; sq += rq[i]; }
    float mean = sum * (1.f / Dm);
    float var  = sq * (1.f / Dm) - mean * mean;
    float inv  = rsqrtf(var + 1e-5f);
    const float* ms = mod + (row / Tq) * (6 * Dm);
    int d = tid * 4;
    float in[4] = {v.x, v.y, v.z, v.w};
    float4 ov;
    float* po = (float*)&ov;
    #pragma unroll
    for (int e = 0; e < 4; e++) {
        float xn = (in[e] - mean) * inv * w[d + e] + bvec[d + e];
        po[e] = xn * (1.f + ms[scaleOff + d + e]) + ms[shiftOff + d + e];
    }
    ((float4*)(out + (size_t)row * Dm))[tid] = ov;
}

// ---------------- RoPE table ----------------
__global__ void rope_table_kernel(float* __restrict__ c, float* __restrict__ s)
{
    int pos = blockIdx.x, j = threadIdx.x;
    float ang = (float)pos * expf(-(float)j * (9.2103403719761836f / 32.f));
    float sn, cs;
    sincosf(ang, &sn, &cs);
    c[pos * 32 + j] = cs;
    s[pos * 32 + j] = sn;
}

// -------- QK post, merged: q0 rows [0,MR), qad [MR,4MR), kcat [4MR,4MR+NB*KTOT)
__global__ __launch_bounds__(256) void qkpost_all_kernel(
    float* __restrict__ q0, float* __restrict__ qad, float* __restrict__ kcat,
    const float* __restrict__ qn_w, const float* __restrict__ kn_w,
    const float* __restrict__ rc, const float* __restrict__ rs)
{
    int row = blockIdx.x, tid = threadIdx.x;
    float* rp;
    const float* w;
    int pos;
    if (row < MR) {
        rp = q0 + (size_t)row * Dm; w = qn_w; pos = row & (Tq - 1);
    } else if (row < 4 * MR) {
        rp = qad + (size_t)(row - MR) * Dm; w = qn_w; pos = -1;
    } else {
        int r = row - 4 * MR;
        rp = kcat + (size_t)r * Dm; w = kn_w;
        int rr = r % KTOT;
        pos = (rr < 512) ? rr : (rr < 1024) ? rr - 512 : (rr < 1536) ? rr - 1024 : rr - 1536;
    }
    float4 v = ((float4*)rp)[tid];
    float ss = v.x * v.x + v.y * v.y + v.z * v.z + v.w * v.w;
    ss += __shfl_xor_sync(~0u, ss, 1, 16);
    ss += __shfl_xor_sync(~0u, ss, 2, 16);
    ss += __shfl_xor_sync(~0u, ss, 4, 16);
    ss += __shfl_xor_sync(~0u, ss, 8, 16);
    float inv = rsqrtf(ss * (1.f / 64.f) + 1e-6f);
    int dl = (tid & 15) * 4;
    float nv[4] = {v.x * inv * w[dl], v.y * inv * w[dl + 1],
                   v.z * inv * w[dl + 2], v.w * inv * w[dl + 3]};
    if (pos >= 0) {
        float pv[4];
        #pragma unroll
        for (int e = 0; e < 4; e++) pv[e] = __shfl_xor_sync(~0u, nv[e], 8, 16);
        bool firstHalf = dl < 32;
        int jb = dl & 31;
        float4 c4 = *(const float4*)&rc[pos * 32 + jb];
        float4 s4 = *(const float4*)&rs[pos * 32 + jb];
        float cse[4] = {c4.x, c4.y, c4.z, c4.w};
        float sne[4] = {s4.x, s4.y, s4.z, s4.w};
        #pragma unroll
        for (int e = 0; e < 4; e++) {
            nv[e] = firstHalf ? (nv[e] * cse[e] - pv[e] * sne[e])
                              : (nv[e] * cse[e] + pv[e] * sne[e]);
        }
    }
    float4 o = {nv[0], nv[1], nv[2], nv[3]};
    ((float4*)rp)[tid] = o;
}

// ============ Flash attention, tf32 mma + 3-stage cp.async K/V pipeline =====
// 128 queries x 1 head per CTA (256 threads, 8 warps, 16q x 64kk warp tile).
// K/V tiles contiguous across segments -> single prefetch stream, now with
// prefetch distance 2 (3 buffers, wait_group 1). Layouts: Qs/Ks stride 84,
// Vs stride 72 (bank-conflict-free fragment loads).
#define QKS 84
#define VS  72
#define KVSTG (64 * QKS + 64 * VS)
#define FLASH_SMEM ((128 * QKS + 3 * KVSTG) * 4)

__global__ __launch_bounds__(256) void flash_mma_kernel(
    const float* __restrict__ q0p, const float* __restrict__ q1p,
    const float* __restrict__ q2p, const float* __restrict__ q3p,
    const float* __restrict__ kcat, const float* __restrict__ vcat,
    const float* __restrict__ temps, const float* __restrict__ sbias,
    const float* __restrict__ gating, float* __restrict__ outp)
{
    extern __shared__ float sm[];
    float* Qs  = sm;                    // [128][84]
    float* KV0 = sm + 128 * QKS;        // 3 stages: K [64][84] + V [64][72]

    int tid = threadIdx.x;
    int wid = tid >> 5, lane = tid & 31;
    int g = lane >> 2, tc = lane & 3;
    int q0w = wid * 16;                 // 0..112
    int h = blockIdx.y, b = blockIdx.z;
    int qbase = b * Tq + blockIdx.x * 128;

    const float* qp[4] = {q0p, q1p, q2p, q3p};
    float rg = tanhf(gating[0]);

    float m0 = -1e30f, m1 = -1e30f, l0 = 0.f, l1 = 0.f;
    float Oacc[8][4];
    #pragma unroll
    for (int dt = 0; dt < 8; dt++)
        #pragma unroll
        for (int e = 0; e < 4; e++) Oacc[dt][e] = 0.f;

    // KV staging: 256 threads cover 64 rows x 64 d; 16 floats each
    int sr  = tid & 63;
    int scb = (tid >> 6) * 16;          // 0,16,32,48
    uint32_t kd0 = (uint32_t)__cvta_generic_to_shared(KV0 + sr * QKS + scb);
    uint32_t vd0 = (uint32_t)__cvta_generic_to_shared(KV0 + 64 * QKS + sr * VS + scb);
    const float* srcK0 = kcat + (size_t)(b * KTOT + sr) * Dm + h * HDm + scb;
    const float* srcV0 = vcat + (size_t)(b * KTOT + sr) * Dm + h * HDm + scb;

    // Q staging: 256 threads cover 128 rows x 64 d; 32 floats each
    int qr  = tid >> 1;
    int qcb = (tid & 1) * 32;

    int srcA = (lane & ~3) | (tc >> 1);
    int srcB = srcA + 2;
    bool odd = tc & 1;

    auto issue_kv = [&](int t) {
        uint32_t off = (uint32_t)(t % 3) * (KVSTG * 4);
        const float* sk = srcK0 + (size_t)t * 64 * Dm;
        const float* sv = srcV0 + (size_t)t * 64 * Dm;
        #pragma unroll
        for (int j = 0; j < 4; j++) {
            cpa16(kd0 + off + j * 16, sk + j * 4);
            cpa16(vd0 + off + j * 16, sv + j * 4);
        }
    };

    issue_kv(0); CP_COMMIT();
    issue_kv(1); CP_COMMIT();
    int t = 0;

    for (int seg = 0; seg < 4; seg++) {
        float tt = temps[seg];
        float sp = tt > 20.f ? tt : log1pf(expf(tt));
        float scale = 0.125f * (1.f + sp);
        float sb = sbias[seg];
        if (seg == 3) { scale *= rg; sb *= rg; }

        // stage Q variant (natural [q][d]); Qs untouched by kv pipeline
        __syncthreads();
        {
            const float* src = qp[seg] + (size_t)(qbase + qr) * Dm + h * HDm + qcb;
            float* qd = &Qs[qr * QKS + qcb];
            #pragma unroll
            for (int j4 = 0; j4 < 8; j4++)
                *(float4*)(qd + j4 * 4) = ((const float4*)src)[j4];
        }
        __syncthreads();
        // preload Q fragments (reused for all k-tiles of this segment)
        uint32_t qf[8][4];
        #pragma unroll
        for (int c = 0; c < 8; c++) {
            qf[c][0] = __float_as_uint(Qs[(q0w + g) * QKS + c * 8 + tc]);
            qf[c][1] = __float_as_uint(Qs[(q0w + g + 8) * QKS + c * 8 + tc]);
            qf[c][2] = __float_as_uint(Qs[(q0w + g) * QKS + c * 8 + tc + 4]);
            qf[c][3] = __float_as_uint(Qs[(q0w + g + 8) * QKS + c * 8 + tc + 4]);
        }

        int nt = (seg == 3) ? 4 : 8;
        for (int kt = 0; kt < nt; kt++, t++) {
            CP_WAIT1();
            __syncthreads();
            if (t + 2 < 28) issue_kv(t + 2);
            CP_COMMIT();

            const float* Ks = KV0 + (t % 3) * KVSTG;
            const float* Vs = Ks + 64 * QKS;

            // ---- S = Q K^T (16q x 64kk per warp) ----
            float S[8][4];
            #pragma unroll
            for (int ni = 0; ni < 8; ni++)
                #pragma unroll
                for (int e = 0; e < 4; e++) S[ni][e] = 0.f;
            #pragma unroll
            for (int c = 0; c < 8; c++) {
                #pragma unroll
                for (int ni = 0; ni < 8; ni++) {
                    uint32_t bf[2];
                    bf[0] = __float_as_uint(Ks[(ni * 8 + g) * QKS + c * 8 + tc]);
                    bf[1] = __float_as_uint(Ks[(ni * 8 + g) * QKS + c * 8 + tc + 4]);
                    mma8(S[ni], qf[c], bf);
                }
            }

            // ---- online softmax (rows g, g+8 of warp tile) ----
            float r0 = -1e30f, r1 = -1e30f;
            #pragma unroll
            for (int ni = 0; ni < 8; ni++) {
                S[ni][0] = fmaf(S[ni][0], scale, sb);
                S[ni][1] = fmaf(S[ni][1], scale, sb);
                S[ni][2] = fmaf(S[ni][2], scale, sb);
                S[ni][3] = fmaf(S[ni][3], scale, sb);
                r0 = fmaxf(r0, fmaxf(S[ni][0], S[ni][1]));
                r1 = fmaxf(r1, fmaxf(S[ni][2], S[ni][3]));
            }
            r0 = fmaxf(r0, __shfl_xor_sync(~0u, r0, 1));
            r0 = fmaxf(r0, __shfl_xor_sync(~0u, r0, 2));
            r1 = fmaxf(r1, __shfl_xor_sync(~0u, r1, 1));
            r1 = fmaxf(r1, __shfl_xor_sync(~0u, r1, 2));
            float mn0 = fmaxf(m0, r0), mn1 = fmaxf(m1, r1);
            float f0 = __expf(m0 - mn0), f1 = __expf(m1 - mn1);
            float s0 = 0.f, s1 = 0.f;
            #pragma unroll
            for (int ni = 0; ni < 8; ni++) {
                S[ni][0] = __expf(S[ni][0] - mn0);
                S[ni][1] = __expf(S[ni][1] - mn0);
                S[ni][2] = __expf(S[ni][2] - mn1);
                S[ni][3] = __expf(S[ni][3] - mn1);
                s0 += S[ni][0] + S[ni][1];
                s1 += S[ni][2] + S[ni][3];
            }
            s0 += __shfl_xor_sync(~0u, s0, 1);
            s0 += __shfl_xor_sync(~0u, s0, 2);
            s1 += __shfl_xor_sync(~0u, s1, 1);
            s1 += __shfl_xor_sync(~0u, s1, 2);
            l0 = l0 * f0 + s0;
            l1 = l1 * f1 + s1;
            m0 = mn0; m1 = mn1;
            #pragma unroll
            for (int dt = 0; dt < 8; dt++) {
                Oacc[dt][0] *= f0; Oacc[dt][1] *= f0;
                Oacc[dt][2] *= f1; Oacc[dt][3] *= f1;
            }

            // ---- O += P V  (P from registers via lane transpose) ----
            #pragma unroll
            for (int ni = 0; ni < 8; ni++) {
                float p0 = S[ni][0], p1 = S[ni][1];
                float p2 = S[ni][2], p3 = S[ni][3];
                float x0 = __shfl_sync(~0u, p0, srcA), y0 = __shfl_sync(~0u, p1, srcA);
                float x2 = __shfl_sync(~0u, p0, srcB), y2 = __shfl_sync(~0u, p1, srcB);
                float x1 = __shfl_sync(~0u, p2, srcA), y1 = __shfl_sync(~0u, p3, srcA);
                float x3 = __shfl_sync(~0u, p2, srcB), y3 = __shfl_sync(~0u, p3, srcB);
                uint32_t ap[4];
                ap[0] = __float_as_uint(odd ? y0 : x0);
                ap[1] = __float_as_uint(odd ? y1 : x1);
                ap[2] = __float_as_uint(odd ? y2 : x2);
                ap[3] = __float_as_uint(odd ? y3 : x3);
                #pragma unroll
                for (int dt = 0; dt < 8; dt++) {
                    uint32_t bv[2];
                    bv[0] = __float_as_uint(Vs[(ni * 8 + tc) * VS + dt * 8 + g]);
                    bv[1] = __float_as_uint(Vs[(ni * 8 + tc + 4) * VS + dt * 8 + g]);
                    mma8(Oacc[dt], ap, bv);
                }
            }
        }
    }

    float i0 = 1.f / l0, i1 = 1.f / l1;
    int qg0 = qbase + q0w + g, qg1 = qg0 + 8;
    #pragma unroll
    for (int dt = 0; dt < 8; dt++) {
        int dcol = h * HDm + dt * 8 + tc * 2;
        float2 o0 = {Oacc[dt][0] * i0, Oacc[dt][1] * i0};
        float2 o1 = {Oacc[dt][2] * i1, Oacc[dt][3] * i1};
        *(float2*)&outp[(size_t)qg0 * Dm + dcol] = o0;
        *(float2*)&outp[(size_t)qg1 * Dm + dcol] = o1;
    }
}

// ---------------- launch ----------------
static float* symaddr(const void* s) {
    void* p = nullptr;
    cudaGetSymbolAddress(&p, s);
    return (float*)p;
}

extern "C" void kernel_launch(void* const* d_in, const int* in_sizes, int n_in,
                              void* d_out, int out_size)
{
    const float* x        = (const float*)d_in[0];
    const float* bev      = (const float*)d_in[1];
    const float* vl       = (const float*)d_in[2];
    const float* reas     = (const float*)d_in[3];
    const float* cond     = (const float*)d_in[4];
    const float* ln_pre_w = (const float*)d_in[5];
    const float* ln_pre_b = (const float*)d_in[6];
    const float* adaln_w  = (const float*)d_in[7];
    const float* adaln_b  = (const float*)d_in[8];
    const float* q_proj_w = (const float*)d_in[9];
    const float* q_proj_b = (const float*)d_in[10];
    const float* qa_w     = (const float*)d_in[11];
    const float* qa_b     = (const float*)d_in[12];
    const float* qa_out_w = (const float*)d_in[13];
    const float* qa_out_b = (const float*)d_in[14];
    const float* k_w      = (const float*)d_in[15];
    const float* k_b      = (const float*)d_in[16];
    const float* v_w      = (const float*)d_in[17];
    const float* v_b      = (const float*)d_in[18];
    const float* o_w      = (const float*)d_in[19];
    const float* o_b      = (const float*)d_in[20];
    const float* qn_w     = (const float*)d_in[21];
    const float* kn_w     = (const float*)d_in[22];
    const float* gating   = (const float*)d_in[23];
    const float* temps    = (const float*)d_in[24];
    const float* sbias    = (const float*)d_in[25];
    const float* ffn_ln_w = (const float*)d_in[26];
    const float* ffn_ln_b = (const float*)d_in[27];
    const float* ffn_w1   = (const float*)d_in[28];
    const float* ffn_b1   = (const float*)d_in[29];
    const float* ffn_w2   = (const float*)d_in[30];
    const float* ffn_b2   = (const float*)d_in[31];
    float* out = (float*)d_out;

    float* p_mod    = symaddr(g_mod);
    float* p_xnorm  = symaddr(g_xnorm);
    float* p_q0     = symaddr(g_q0);
    float* p_qad    = symaddr(g_qad);
    float* p_hidden = symaddr(g_hidden);
    float* p_kcat   = symaddr(g_kcat);
    float* p_vcat   = symaddr(g_vcat);
    float* p_attn   = symaddr(g_attnout);
    float* p_xa     = symaddr(g_xa);
    float* p_hln    = symaddr(g_hln);
    float* p_hff    = symaddr(g_hff);
    float* p_rcos   = symaddr(g_rcos);
    float* p_rsin   = symaddr(g_rsin);

    cudaFuncSetAttribute(kvq_kernel, cudaFuncAttributeMaxDynamicSharedMemorySize, GEMM_SMEM);
    cudaFuncSetAttribute(adapter_o_kernel, cudaFuncAttributeMaxDynamicSharedMemorySize, GEMM_SMEM);
    cudaFuncSetAttribute(gemm_kernel<2, 1024, 1024>, cudaFuncAttributeMaxDynamicSharedMemorySize, GEMM_SMEM);
    cudaFuncSetAttribute(gemm_kernel<1, 1024, 4096>, cudaFuncAttributeMaxDynamicSharedMemorySize, GEMM_SMEM);
    cudaFuncSetAttribute(gemm_kernel<2, 4096, 1024>, cudaFuncAttributeMaxDynamicSharedMemorySize, GEMM_SMEM);
    cudaFuncSetAttribute(flash_mma_kernel, cudaFuncAttributeMaxDynamicSharedMemorySize, FLASH_SMEM);

    // 0) RoPE tables
    rope_table_kernel<<<Tq, 32>>>(p_rcos, p_rsin);

    // 1) AdaLN modulation
    mod_kernel<<<dim3(6 * Dm / 8, NB), 256>>>(cond, adaln_w, adaln_b, p_mod);

    // 2) pre-LN + modulate
    ln_mod_kernel<<<MR, 256>>>(x, ln_pre_w, ln_pre_b, p_mod, 0, Dm, p_xnorm);

    // 3) K/V (4 sources) + Q + adapter hidden, one batched launch
    kvq_kernel<<<dim3(8, 16, 12), 256, GEMM_SMEM>>>(
        p_xnorm, bev, vl, reas, k_w, k_b, v_w, v_b, q_proj_w, q_proj_b,
        qa_w, qa_b, p_kcat, p_vcat, p_q0, p_hidden);

    // 4) adapter out (batched over 3)
    adapter_o_kernel<<<dim3(8, 16, 3), 256, GEMM_SMEM>>>(p_hidden, qa_out_w, qa_out_b, p_qad);

    // 5) QK-norm + RoPE (single merged launch)
    qkpost_all_kernel<<<4 * MR + NB * KTOT, 256>>>(
        p_q0, p_qad, p_kcat, qn_w, kn_w, p_rcos, p_rsin);

    // 6) flash attention (tf32 mma, 128-q CTAs, 3-stage cp.async K/V)
    flash_mma_kernel<<<dim3(Tq / 128, NH, NB), 256, FLASH_SMEM>>>(
        p_q0, p_qad, p_qad + (size_t)MR * Dm, p_qad + (size_t)2 * MR * Dm,
        p_kcat, p_vcat, temps, sbias, gating, p_attn);

    // 7) o-proj + residual + gate_attn
    gemm_kernel<2, 1024, 1024><<<dim3(8, 16), 256, GEMM_SMEM>>>(
        p_attn, o_w, o_b, p_xa, x, p_mod, 2 * Dm);

    // 8) FFN
    ln_mod_kernel<<<MR, 256>>>(p_xa, ffn_ln_w, ffn_ln_b, p_mod, 3 * Dm, 4 * Dm, p_hln);
    gemm_kernel<1, 1024, 4096><<<dim3(32, 16), 256, GEMM_SMEM>>>(
        p_hln, ffn_w1, ffn_b1, p_hff, nullptr, nullptr, 0);
    gemm_kernel<2, 4096, 1024><<<dim3(8, 16), 256, GEMM_SMEM>>>(
        p_hff, ffn_w2, ffn_b2, out, p_xa, p_mod, 5 * Dm);
}

// round 17
// speedup vs baseline: 2.2295x; 1.4503x over previous
#include <cuda_runtime.h>
#include <cuda_fp16.h>
#include <math.h>
#include <stdint.h>

// ---------------- problem constants ----------------
#define Dm   1024
#define Tq   512
#define NB   4
#define NH   16
#define HDm  64
#define KTOT 1792
#define MR   2048        // NB*Tq rows
#define DFF  4096

// ---------------- scratch (device globals; no allocation) ----------------
__device__ float g_mod[NB * 6 * Dm];
__device__ float g_q0[MR * Dm];
__device__ float g_qad[3 * MR * Dm];
__device__ float g_kcat[NB * KTOT * Dm];
__device__ float g_vcat[NB * KTOT * Dm];
__device__ float g_xa[MR * Dm];
__device__ float g_rcos[Tq * 32];
__device__ float g_rsin[Tq * 32];

// fp16 activation / weight arenas
__device__ __half h_xnorm[MR * Dm];
__device__ __half h_hidden[3 * MR * 256];
__device__ __half h_attn[MR * Dm];
__device__ __half h_hln[MR * Dm];
__device__ __half h_hff[MR * DFF];
__device__ __half h_bev[NB * 512 * Dm];
__device__ __half h_vl[NB * 512 * Dm];
__device__ __half h_reas[NB * 256 * Dm];
__device__ __half h_qw[Dm * Dm];
__device__ __half h_kw[4 * Dm * Dm];
__device__ __half h_vw[4 * Dm * Dm];
__device__ __half h_qaw[3 * 256 * Dm];
__device__ __half h_qaow[Dm * 256];
__device__ __half h_ow[Dm * Dm];
__device__ __half h_w1[DFF * Dm];
__device__ __half h_w2[Dm * DFF];

// ---------------- helpers ----------------
__device__ __forceinline__ void mma8(float* c, const uint32_t* a, const uint32_t* b) {
    asm volatile(
        "mma.sync.aligned.m16n8k8.row.col.f32.tf32.tf32.f32 "
        "{%0,%1,%2,%3},{%4,%5,%6,%7},{%8,%9},{%0,%1,%2,%3};\n"
        : "+f"(c[0]), "+f"(c[1]), "+f"(c[2]), "+f"(c[3])
        : "r"(a[0]), "r"(a[1]), "r"(a[2]), "r"(a[3]), "r"(b[0]), "r"(b[1]));
}

__device__ __forceinline__ void mma16(float* c, const uint32_t* a, const uint32_t* b) {
    asm volatile(
        "mma.sync.aligned.m16n8k16.row.col.f32.f16.f16.f32 "
        "{%0,%1,%2,%3},{%4,%5,%6,%7},{%8,%9},{%0,%1,%2,%3};\n"
        : "+f"(c[0]), "+f"(c[1]), "+f"(c[2]), "+f"(c[3])
        : "r"(a[0]), "r"(a[1]), "r"(a[2]), "r"(a[3]), "r"(b[0]), "r"(b[1]));
}

__device__ __forceinline__ void cpa16(uint32_t dst, const void* src) {
    asm volatile("cp.async.cg.shared.global [%0], [%1], 16;\n" :: "r"(dst), "l"(src));
}
#define CP_COMMIT() asm volatile("cp.async.commit_group;\n" ::)
#define CP_WAIT1()  asm volatile("cp.async.wait_group 1;\n" ::: "memory")

// ---------------- f32 -> f16 conversion ----------------
__global__ __launch_bounds__(256) void cvt_h_kernel(const float* __restrict__ s,
                                                    __half* __restrict__ d, int n)
{
    int i = (blockIdx.x * 256 + threadIdx.x) * 4;
    if (i < n) {
        float4 v = *(const float4*)(s + i);
        __half2 h0 = __floats2half2_rn(v.x, v.y);
        __half2 h1 = __floats2half2_rn(v.z, v.w);
        *(__half2*)(d + i) = h0;
        *(__half2*)(d + i + 2) = h1;
    }
}

// ================== fp16 GEMM core: C = A @ W^T + bias (+ epilogue) =========
// 3-stage cp.async pipeline. Shared layout [m][k-half], row stride 24 halves
// (12 words): fragment-word banks 12g+tc (+4) bijective -> conflict-free.
// m16n8k16 f16 mma, f32 accum. Tile 128x128x16, 8 warps each 64x32.
#define HSTG  (128 * 24)                 // halves per stage per operand
#define GEMM_SMEM (2 * 3 * HSTG * 2)     // bytes

template<int EPI, int OUTH, int Kc, int Nc>
__device__ __forceinline__ void gemm_core(
    const __half* __restrict__ A, const __half* __restrict__ W,
    const float* __restrict__ bias, void* __restrict__ Cv,
    int Lb, int outBatchRows, int outRowOff,
    const float* __restrict__ res, const float* __restrict__ mod, int gateOff,
    float* smf)
{
    __half* As = (__half*)smf;
    __half* Bs = As + 3 * HSTG;

    int tid  = threadIdx.x;
    int wid  = tid >> 5;
    int lane = tid & 31;
    int g  = lane >> 2;      // 0..7
    int tc = lane & 3;       // 0..3
    int warpM = (wid & 1) * 64;
    int warpN = (wid >> 1) * 32;

    int row0 = blockIdx.y * 128;
    int col0 = blockIdx.x * 128;

    int ldRow = tid >> 1;          // 0..127
    int ldCol = (tid & 1) * 8;     // halves: 0 or 8
    const __half* Ag = A + (size_t)(row0 + ldRow) * Kc + ldCol;
    const __half* Wg = W + (size_t)(col0 + ldRow) * Kc + ldCol;
    uint32_t sAd = (uint32_t)__cvta_generic_to_shared(As + ldRow * 24 + ldCol);
    uint32_t sBd = (uint32_t)__cvta_generic_to_shared(Bs + ldRow * 24 + ldCol);

    const int NIT = Kc >> 4;

    float acc[4][4][4];
    #pragma unroll
    for (int mi = 0; mi < 4; mi++)
        #pragma unroll
        for (int ni = 0; ni < 4; ni++)
            #pragma unroll
            for (int e = 0; e < 4; e++) acc[mi][ni][e] = 0.f;

    auto issue = [&](int it) {
        uint32_t off = (uint32_t)(it % 3) * (HSTG * 2);
        cpa16(sAd + off, Ag + it * 16);
        cpa16(sBd + off, Wg + it * 16);
    };
    issue(0); CP_COMMIT();
    issue(1); CP_COMMIT();

    #pragma unroll 1
    for (int it = 0; it < NIT; it++) {
        CP_WAIT1();
        __syncthreads();
        if (it + 2 < NIT) issue(it + 2);
        CP_COMMIT();

        const uint32_t* Aw = (const uint32_t*)(As + (it % 3) * HSTG);
        const uint32_t* Bw = (const uint32_t*)(Bs + (it % 3) * HSTG);

        uint32_t af[4][4];
        #pragma unroll
        for (int mi = 0; mi < 4; mi++) {
            int r = warpM + mi * 16 + g;
            af[mi][0] = Aw[r * 12 + tc];
            af[mi][1] = Aw[(r + 8) * 12 + tc];
            af[mi][2] = Aw[r * 12 + tc + 4];
            af[mi][3] = Aw[(r + 8) * 12 + tc + 4];
        }
        uint32_t bf_[4][2];
        #pragma unroll
        for (int ni = 0; ni < 4; ni++) {
            int cN = warpN + ni * 8 + g;
            bf_[ni][0] = Bw[cN * 12 + tc];
            bf_[ni][1] = Bw[cN * 12 + tc + 4];
        }
        #pragma unroll
        for (int mi = 0; mi < 4; mi++)
            #pragma unroll
            for (int ni = 0; ni < 4; ni++)
                mma16(acc[mi][ni], af[mi], bf_[ni]);
    }

    // epilogue
    #pragma unroll
    for (int mi = 0; mi < 4; mi++) {
        #pragma unroll
        for (int ib = 0; ib < 2; ib++) {
            int m = row0 + warpM + mi * 16 + g + ib * 8;
            int orow = (m / Lb) * outBatchRows + outRowOff + (m % Lb);
            const float* resr = (EPI == 2) ? res + (size_t)m * Nc : nullptr;
            const float* gr   = (EPI == 2) ? mod + (m / Tq) * (6 * Dm) + gateOff : nullptr;
            #pragma unroll
            for (int ni = 0; ni < 4; ni++) {
                int n = col0 + warpN + ni * 8 + tc * 2;
                float v0 = acc[mi][ni][ib * 2 + 0] + bias[n];
                float v1 = acc[mi][ni][ib * 2 + 1] + bias[n + 1];
                if (EPI == 1) {
                    v0 = 0.5f * v0 * (1.f + erff(v0 * 0.70710678118654752f));
                    v1 = 0.5f * v1 * (1.f + erff(v1 * 0.70710678118654752f));
                }
                if (EPI == 2) {
                    v0 = resr[n] + gr[n] * v0;
                    v1 = resr[n + 1] + gr[n + 1] * v1;
                }
                if (OUTH) {
                    __half2 h2 = __floats2half2_rn(v0, v1);
                    *(__half2*)&((__half*)Cv)[(size_t)orow * Nc + n] = h2;
                } else {
                    float2 o2 = {v0, v1};
                    *(float2*)&((float*)Cv)[(size_t)orow * Nc + n] = o2;
                }
            }
        }
    }
}

// ---- batched K/V/Q + adapter_h: z=0..3 K, 4..7 V, 8 Q, 9..11 adapter_h ----
__global__ __launch_bounds__(256, 2) void kvq_kernel(
    float* __restrict__ kcat, float* __restrict__ vcat,
    float* __restrict__ q0,
    const float* __restrict__ k_b, const float* __restrict__ v_b,
    const float* __restrict__ qb, const float* __restrict__ qa_b)
{
    extern __shared__ float smg[];
    int z = blockIdx.z;
    if (z >= 9) {
        int a = z - 9;
        if (blockIdx.x >= 2) return;
        gemm_core<0, 1, 1024, 256>(h_xnorm, h_qaw + (size_t)a * 256 * Dm, qa_b + a * 256,
                                   h_hidden + (size_t)a * MR * 256,
                                   1 << 30, 0, 0, nullptr, nullptr, 0, smg);
        return;
    }
    const __half* A; const __half* W; const float* bias; float* C;
    int Lb, oBR, oRO;
    if (z < 8) {
        int src = z & 3;
        if (src == 3 && blockIdx.y >= 8) return;
        A = (src == 0) ? h_xnorm : (src == 1) ? h_bev : (src == 2) ? h_vl : h_reas;
        bool isV = z >= 4;
        W    = (isV ? h_vw : h_kw) + (size_t)src * Dm * Dm;
        bias = (isV ? v_b : k_b) + src * Dm;
        C    = isV ? vcat : kcat;
        Lb = (src == 3) ? 256 : 512;
        oBR = KTOT; oRO = src * 512;
    } else {
        A = h_xnorm; W = h_qw; bias = qb; C = q0;
        Lb = 1 << 30; oBR = 0; oRO = 0;
    }
    gemm_core<0, 0, 1024, 1024>(A, W, bias, C, Lb, oBR, oRO, nullptr, nullptr, 0, smg);
}

// ---- batched adapter out: z = 0..2 ----
__global__ __launch_bounds__(256, 2) void adapter_o_kernel(
    const float* __restrict__ qa_out_b, float* __restrict__ qad)
{
    extern __shared__ float smg[];
    int z = blockIdx.z;
    gemm_core<0, 0, 256, 1024>(h_hidden + (size_t)z * MR * 256, h_qaow, qa_out_b,
                               qad + (size_t)z * MR * Dm,
                               1 << 30, 0, 0, nullptr, nullptr, 0, smg);
}

// ---- generic GEMMs ----
__global__ __launch_bounds__(256, 2) void oproj_kernel(
    const float* __restrict__ o_b, float* __restrict__ xa,
    const float* __restrict__ x, const float* __restrict__ mod)
{
    extern __shared__ float smg[];
    gemm_core<2, 0, 1024, 1024>(h_attn, h_ow, o_b, xa, 1 << 30, 0, 0, x, mod, 2 * Dm, smg);
}
__global__ __launch_bounds__(256, 2) void ffn1_kernel(const float* __restrict__ b1)
{
    extern __shared__ float smg[];
    gemm_core<1, 1, 1024, 4096>(h_hln, h_w1, b1, h_hff, 1 << 30, 0, 0, nullptr, nullptr, 0, smg);
}
__global__ __launch_bounds__(256, 2) void ffn2_kernel(
    const float* __restrict__ b2, float* __restrict__ out,
    const float* __restrict__ xa, const float* __restrict__ mod)
{
    extern __shared__ float smg[];
    gemm_core<2, 0, 4096, 1024>(h_hff, h_w2, b2, out, 1 << 30, 0, 0, xa, mod, 5 * Dm, smg);
}

// ---------------- mod = silu(cond) @ adaln_w^T + adaln_b ----------------
__global__ __launch_bounds__(256) void mod_kernel(const float* __restrict__ cond,
                                                  const float* __restrict__ W,
                                                  const float* __restrict__ bb,
                                                  float* __restrict__ mod)
{
    int b = blockIdx.y;
    __shared__ float sc[Dm];
    for (int i = threadIdx.x; i < Dm; i += 256) {
        float c = cond[b * Dm + i];
        sc[i] = c / (1.f + expf(-c));
    }
    __syncthreads();
    int w = threadIdx.x >> 5, lane = threadIdx.x & 31;
    int n = blockIdx.x * 8 + w;
    const float* wr = W + (size_t)n * Dm;
    float acc = 0.f;
    for (int k = lane; k < Dm; k += 32) acc += sc[k] * wr[k];
    #pragma unroll
    for (int o = 16; o; o >>= 1) acc += __shfl_xor_sync(~0u, acc, o);
    if (lane == 0) mod[b * 6 * Dm + n] = acc + bb[n];
}

// ---------------- LayerNorm + AdaLN modulate (writes fp16) ----------------
__global__ __launch_bounds__(256) void ln_mod_kernel(const float* __restrict__ x,
                                                     const float* __restrict__ w,
                                                     const float* __restrict__ bvec,
                                                     const float* __restrict__ mod,
                                                     int shiftOff, int scaleOff,
                                                     __half* __restrict__ out)
{
    int row = blockIdx.x;
    int tid = threadIdx.x;
    float4 v = ((const float4*)(x + (size_t)row * Dm))[tid];
    float s = v.x + v.y + v.z + v.w;
    float q = v.x * v.x + v.y * v.y + v.z * v.z + v.w * v.w;
    __shared__ float rs[8], rq[8];
    #pragma unroll
    for (int o = 16; o; o >>= 1) {
        s += __shfl_xor_sync(~0u, s, o);
        q += __shfl_xor_sync(~0u, q, o);
    }
    if ((tid & 31) == 0) { rs[tid >> 5] = s; rq[tid >> 5] = q; }
    __syncthreads();
    float sum = 0.f, sq = 0.f;
    #pragma unroll
    for (int i = 0; i < 8; i++) { sum += rs[i]; sq += rq[i]; }
    float mean = sum * (1.f / Dm);
    float var  = sq * (1.f / Dm) - mean * mean;
    float inv  = rsqrtf(var + 1e-5f);
    const float* ms = mod + (row / Tq) * (6 * Dm);
    int d = tid * 4;
    float in[4] = {v.x, v.y, v.z, v.w};
    float po[4];
    #pragma unroll
    for (int e = 0; e < 4; e++) {
        float xn = (in[e] - mean) * inv * w[d + e] + bvec[d + e];
        po[e] = xn * (1.f + ms[scaleOff + d + e]) + ms[shiftOff + d + e];
    }
    __half* op = out + (size_t)row * Dm + d;
    *(__half2*)op       = __floats2half2_rn(po[0], po[1]);
    *(__half2*)(op + 2) = __floats2half2_rn(po[2], po[3]);
}

// ---------------- RoPE table ----------------
__global__ void rope_table_kernel(float* __restrict__ c, float* __restrict__ s)
{
    int pos = blockIdx.x, j = threadIdx.x;
    float ang = (float)pos * expf(-(float)j * (9.2103403719761836f / 32.f));
    float sn, cs;
    sincosf(ang, &sn, &cs);
    c[pos * 32 + j] = cs;
    s[pos * 32 + j] = sn;
}

// -------- QK post, merged: q0 rows [0,MR), qad [MR,4MR), kcat [4MR,4MR+NB*KTOT)
__global__ __launch_bounds__(256) void qkpost_all_kernel(
    float* __restrict__ q0, float* __restrict__ qad, float* __restrict__ kcat,
    const float* __restrict__ qn_w, const float* __restrict__ kn_w,
    const float* __restrict__ rc, const float* __restrict__ rs)
{
    int row = blockIdx.x, tid = threadIdx.x;
    float* rp;
    const float* w;
    int pos;
    if (row < MR) {
        rp = q0 + (size_t)row * Dm; w = qn_w; pos = row & (Tq - 1);
    } else if (row < 4 * MR) {
        rp = qad + (size_t)(row - MR) * Dm; w = qn_w; pos = -1;
    } else {
        int r = row - 4 * MR;
        rp = kcat + (size_t)r * Dm; w = kn_w;
        int rr = r % KTOT;
        pos = (rr < 512) ? rr : (rr < 1024) ? rr - 512 : (rr < 1536) ? rr - 1024 : rr - 1536;
    }
    float4 v = ((float4*)rp)[tid];
    float ss = v.x * v.x + v.y * v.y + v.z * v.z + v.w * v.w;
    ss += __shfl_xor_sync(~0u, ss, 1, 16);
    ss += __shfl_xor_sync(~0u, ss, 2, 16);
    ss += __shfl_xor_sync(~0u, ss, 4, 16);
    ss += __shfl_xor_sync(~0u, ss, 8, 16);
    float inv = rsqrtf(ss * (1.f / 64.f) + 1e-6f);
    int dl = (tid & 15) * 4;
    float nv[4] = {v.x * inv * w[dl], v.y * inv * w[dl + 1],
                   v.z * inv * w[dl + 2], v.w * inv * w[dl + 3]};
    if (pos >= 0) {
        float pv[4];
        #pragma unroll
        for (int e = 0; e < 4; e++) pv[e] = __shfl_xor_sync(~0u, nv[e], 8, 16);
        bool firstHalf = dl < 32;
        int jb = dl & 31;
        float4 c4 = *(const float4*)&rc[pos * 32 + jb];
        float4 s4 = *(const float4*)&rs[pos * 32 + jb];
        float cse[4] = {c4.x, c4.y, c4.z, c4.w};
        float sne[4] = {s4.x, s4.y, s4.z, s4.w};
        #pragma unroll
        for (int e = 0; e < 4; e++) {
            nv[e] = firstHalf ? (nv[e] * cse[e] - pv[e] * sne[e])
                              : (nv[e] * cse[e] + pv[e] * sne[e]);
        }
    }
    float4 o = {nv[0], nv[1], nv[2], nv[3]};
    ((float4*)rp)[tid] = o;
}

// ============ Flash attention, tf32 mma + 3-stage cp.async K/V pipeline =====
// (unchanged math; output written as fp16 for the o-proj GEMM)
#define QKS 84
#define VS  72
#define KVSTG (64 * QKS + 64 * VS)
#define FLASH_SMEM ((128 * QKS + 3 * KVSTG) * 4)

__global__ __launch_bounds__(256) void flash_mma_kernel(
    const float* __restrict__ q0p, const float* __restrict__ q1p,
    const float* __restrict__ q2p, const float* __restrict__ q3p,
    const float* __restrict__ kcat, const float* __restrict__ vcat,
    const float* __restrict__ temps, const float* __restrict__ sbias,
    const float* __restrict__ gating, __half* __restrict__ outp)
{
    extern __shared__ float sm[];
    float* Qs  = sm;                    // [128][84]
    float* KV0 = sm + 128 * QKS;        // 3 stages: K [64][84] + V [64][72]

    int tid = threadIdx.x;
    int wid = tid >> 5, lane = tid & 31;
    int g = lane >> 2, tc = lane & 3;
    int q0w = wid * 16;
    int h = blockIdx.y, b = blockIdx.z;
    int qbase = b * Tq + blockIdx.x * 128;

    const float* qp[4] = {q0p, q1p, q2p, q3p};
    float rg = tanhf(gating[0]);

    float m0 = -1e30f, m1 = -1e30f, l0 = 0.f, l1 = 0.f;
    float Oacc[8][4];
    #pragma unroll
    for (int dt = 0; dt < 8; dt++)
        #pragma unroll
        for (int e = 0; e < 4; e++) Oacc[dt][e] = 0.f;

    int sr  = tid & 63;
    int scb = (tid >> 6) * 16;
    uint32_t kd0 = (uint32_t)__cvta_generic_to_shared(KV0 + sr * QKS + scb);
    uint32_t vd0 = (uint32_t)__cvta_generic_to_shared(KV0 + 64 * QKS + sr * VS + scb);
    const float* srcK0 = kcat + (size_t)(b * KTOT + sr) * Dm + h * HDm + scb;
    const float* srcV0 = vcat + (size_t)(b * KTOT + sr) * Dm + h * HDm + scb;

    int qr  = tid >> 1;
    int qcb = (tid & 1) * 32;

    int srcA = (lane & ~3) | (tc >> 1);
    int srcB = srcA + 2;
    bool odd = tc & 1;

    auto issue_kv = [&](int t) {
        uint32_t off = (uint32_t)(t % 3) * (KVSTG * 4);
        const float* sk = srcK0 + (size_t)t * 64 * Dm;
        const float* sv = srcV0 + (size_t)t * 64 * Dm;
        #pragma unroll
        for (int j = 0; j < 4; j++) {
            cpa16(kd0 + off + j * 16, sk + j * 4);
            cpa16(vd0 + off + j * 16, sv + j * 4);
        }
    };

    issue_kv(0); CP_COMMIT();
    issue_kv(1); CP_COMMIT();
    int t = 0;

    for (int seg = 0; seg < 4; seg++) {
        float tt = temps[seg];
        float sp = tt > 20.f ? tt : log1pf(expf(tt));
        float scale = 0.125f * (1.f + sp);
        float sb = sbias[seg];
        if (seg == 3) { scale *= rg; sb *= rg; }

        __syncthreads();
        {
            const float* src = qp[seg] + (size_t)(qbase + qr) * Dm + h * HDm + qcb;
            float* qd = &Qs[qr * QKS + qcb];
            #pragma unroll
            for (int j4 = 0; j4 < 8; j4++)
                *(float4*)(qd + j4 * 4) = ((const float4*)src)[j4];
        }
        __syncthreads();
        uint32_t qf[8][4];
        #pragma unroll
        for (int c = 0; c < 8; c++) {
            qf[c][0] = __float_as_uint(Qs[(q0w + g) * QKS + c * 8 + tc]);
            qf[c][1] = __float_as_uint(Qs[(q0w + g + 8) * QKS + c * 8 + tc]);
            qf[c][2] = __float_as_uint(Qs[(q0w + g) * QKS + c * 8 + tc + 4]);
            qf[c][3] = __float_as_uint(Qs[(q0w + g + 8) * QKS + c * 8 + tc + 4]);
        }

        int nt = (seg == 3) ? 4 : 8;
        for (int kt = 0; kt < nt; kt++, t++) {
            CP_WAIT1();
            __syncthreads();
            if (t + 2 < 28) issue_kv(t + 2);
            CP_COMMIT();

            const float* Ks = KV0 + (t % 3) * KVSTG;
            const float* Vs = Ks + 64 * QKS;

            float S[8][4];
            #pragma unroll
            for (int ni = 0; ni < 8; ni++)
                #pragma unroll
                for (int e = 0; e < 4; e++) S[ni][e] = 0.f;
            #pragma unroll
            for (int c = 0; c < 8; c++) {
                #pragma unroll
                for (int ni = 0; ni < 8; ni++) {
                    uint32_t bf[2];
                    bf[0] = __float_as_uint(Ks[(ni * 8 + g) * QKS + c * 8 + tc]);
                    bf[1] = __float_as_uint(Ks[(ni * 8 + g) * QKS + c * 8 + tc + 4]);
                    mma8(S[ni], qf[c], bf);
                }
            }

            float r0 = -1e30f, r1 = -1e30f;
            #pragma unroll
            for (int ni = 0; ni < 8; ni++) {
                S[ni][0] = fmaf(S[ni][0], scale, sb);
                S[ni][1] = fmaf(S[ni][1], scale, sb);
                S[ni][2] = fmaf(S[ni][2], scale, sb);
                S[ni][3] = fmaf(S[ni][3], scale, sb);
                r0 = fmaxf(r0, fmaxf(S[ni][0], S[ni][1]));
                r1 = fmaxf(r1, fmaxf(S[ni][2], S[ni][3]));
            }
            r0 = fmaxf(r0, __shfl_xor_sync(~0u, r0, 1));
            r0 = fmaxf(r0, __shfl_xor_sync(~0u, r0, 2));
            r1 = fmaxf(r1, __shfl_xor_sync(~0u, r1, 1));
            r1 = fmaxf(r1, __shfl_xor_sync(~0u, r1, 2));
            float mn0 = fmaxf(m0, r0), mn1 = fmaxf(m1, r1);
            float f0 = __expf(m0 - mn0), f1 = __expf(m1 - mn1);
            float s0 = 0.f, s1 = 0.f;
            #pragma unroll
            for (int ni = 0; ni < 8; ni++) {
                S[ni][0] = __expf(S[ni][0] - mn0);
                S[ni][1] = __expf(S[ni][1] - mn0);
                S[ni][2] = __expf(S[ni][2] - mn1);
                S[ni][3] = __expf(S[ni][3] - mn1);
                s0 += S[ni][0] + S[ni][1];
                s1 += S[ni][2] + S[ni][3];
            }
            s0 += __shfl_xor_sync(~0u, s0, 1);
            s0 += __shfl_xor_sync(~0u, s0, 2);
            s1 += __shfl_xor_sync(~0u, s1, 1);
            s1 += __shfl_xor_sync(~0u, s1, 2);
            l0 = l0 * f0 + s0;
            l1 = l1 * f1 + s1;
            m0 = mn0; m1 = mn1;
            #pragma unroll
            for (int dt = 0; dt < 8; dt++) {
                Oacc[dt][0] *= f0; Oacc[dt][1] *= f0;
                Oacc[dt][2] *= f1; Oacc[dt][3] *= f1;
            }

            #pragma unroll
            for (int ni = 0; ni < 8; ni++) {
                float p0 = S[ni][0], p1 = S[ni][1];
                float p2 = S[ni][2], p3 = S[ni][3];
                float x0 = __shfl_sync(~0u, p0, srcA), y0 = __shfl_sync(~0u, p1, srcA);
                float x2 = __shfl_sync(~0u, p0, srcB), y2 = __shfl_sync(~0u, p1, srcB);
                float x1 = __shfl_sync(~0u, p2, srcA), y1 = __shfl_sync(~0u, p3, srcA);
                float x3 = __shfl_sync(~0u, p2, srcB), y3 = __shfl_sync(~0u, p3, srcB);
                uint32_t ap[4];
                ap[0] = __float_as_uint(odd ? y0 : x0);
                ap[1] = __float_as_uint(odd ? y1 : x1);
                ap[2] = __float_as_uint(odd ? y2 : x2);
                ap[3] = __float_as_uint(odd ? y3 : x3);
                #pragma unroll
                for (int dt = 0; dt < 8; dt++) {
                    uint32_t bv[2];
                    bv[0] = __float_as_uint(Vs[(ni * 8 + tc) * VS + dt * 8 + g]);
                    bv[1] = __float_as_uint(Vs[(ni * 8 + tc + 4) * VS + dt * 8 + g]);
                    mma8(Oacc[dt], ap, bv);
                }
            }
        }
    }

    float i0 = 1.f / l0, i1 = 1.f / l1;
    int qg0 = qbase + q0w + g, qg1 = qg0 + 8;
    #pragma unroll
    for (int dt = 0; dt < 8; dt++) {
        int dcol = h * HDm + dt * 8 + tc * 2;
        *(__half2*)&outp[(size_t)qg0 * Dm + dcol] =
            __floats2half2_rn(Oacc[dt][0] * i0, Oacc[dt][1] * i0);
        *(__half2*)&outp[(size_t)qg1 * Dm + dcol] =
            __floats2half2_rn(Oacc[dt][2] * i1, Oacc[dt][3] * i1);
    }
}

// ---------------- launch ----------------
static void* symaddr(const void* s) {
    void* p = nullptr;
    cudaGetSymbolAddress(&p, s);
    return p;
}

static void cvt(const float* src, const void* dstSym, int n) {
    cvt_h_kernel<<<(n / 4 + 255) / 256, 256>>>(src, (__half*)symaddr(dstSym), n);
}

extern "C" void kernel_launch(void* const* d_in, const int* in_sizes, int n_in,
                              void* d_out, int out_size)
{
    const float* x        = (const float*)d_in[0];
    const float* bev      = (const float*)d_in[1];
    const float* vl       = (const float*)d_in[2];
    const float* reas     = (const float*)d_in[3];
    const float* cond     = (const float*)d_in[4];
    const float* ln_pre_w = (const float*)d_in[5];
    const float* ln_pre_b = (const float*)d_in[6];
    const float* adaln_w  = (const float*)d_in[7];
    const float* adaln_b  = (const float*)d_in[8];
    const float* q_proj_w = (const float*)d_in[9];
    const float* q_proj_b = (const float*)d_in[10];
    const float* qa_w     = (const float*)d_in[11];
    const float* qa_b     = (const float*)d_in[12];
    const float* qa_out_w = (const float*)d_in[13];
    const float* qa_out_b = (const float*)d_in[14];
    const float* k_w      = (const float*)d_in[15];
    const float* k_b      = (const float*)d_in[16];
    const float* v_w      = (const float*)d_in[17];
    const float* v_b      = (const float*)d_in[18];
    const float* o_w      = (const float*)d_in[19];
    const float* o_b      = (const float*)d_in[20];
    const float* qn_w     = (const float*)d_in[21];
    const float* kn_w     = (const float*)d_in[22];
    const float* gating   = (const float*)d_in[23];
    const float* temps    = (const float*)d_in[24];
    const float* sbias    = (const float*)d_in[25];
    const float* ffn_ln_w = (const float*)d_in[26];
    const float* ffn_ln_b = (const float*)d_in[27];
    const float* ffn_w1   = (const float*)d_in[28];
    const float* ffn_b1   = (const float*)d_in[29];
    const float* ffn_w2   = (const float*)d_in[30];
    const float* ffn_b2   = (const float*)d_in[31];
    float* out = (float*)d_out;

    float* p_mod  = (float*)symaddr(g_mod);
    float* p_q0   = (float*)symaddr(g_q0);
    float* p_qad  = (float*)symaddr(g_qad);
    float* p_kcat = (float*)symaddr(g_kcat);
    float* p_vcat = (float*)symaddr(g_vcat);
    float* p_xa   = (float*)symaddr(g_xa);
    float* p_rcos = (float*)symaddr(g_rcos);
    float* p_rsin = (float*)symaddr(g_rsin);
    __half* p_hxnorm = (__half*)symaddr(h_xnorm);
    __half* p_hattn  = (__half*)symaddr(h_attn);
    __half* p_hln    = (__half*)symaddr(h_hln);

    cudaFuncSetAttribute(kvq_kernel, cudaFuncAttributeMaxDynamicSharedMemorySize, GEMM_SMEM);
    cudaFuncSetAttribute(adapter_o_kernel, cudaFuncAttributeMaxDynamicSharedMemorySize, GEMM_SMEM);
    cudaFuncSetAttribute(oproj_kernel, cudaFuncAttributeMaxDynamicSharedMemorySize, GEMM_SMEM);
    cudaFuncSetAttribute(ffn1_kernel, cudaFuncAttributeMaxDynamicSharedMemorySize, GEMM_SMEM);
    cudaFuncSetAttribute(ffn2_kernel, cudaFuncAttributeMaxDynamicSharedMemorySize, GEMM_SMEM);
    cudaFuncSetAttribute(flash_mma_kernel, cudaFuncAttributeMaxDynamicSharedMemorySize, FLASH_SMEM);

    // 0) weight + source conversions to fp16
    cvt(q_proj_w, h_qw, Dm * Dm);
    cvt(k_w, h_kw, 4 * Dm * Dm);
    cvt(v_w, h_vw, 4 * Dm * Dm);
    cvt(qa_w, h_qaw, 3 * 256 * Dm);
    cvt(qa_out_w, h_qaow, Dm * 256);
    cvt(o_w, h_ow, Dm * Dm);
    cvt(ffn_w1, h_w1, DFF * Dm);
    cvt(ffn_w2, h_w2, Dm * DFF);
    cvt(bev, h_bev, NB * 512 * Dm);
    cvt(vl, h_vl, NB * 512 * Dm);
    cvt(reas, h_reas, NB * 256 * Dm);

    // RoPE tables + AdaLN modulation + pre-LN
    rope_table_kernel<<<Tq, 32>>>(p_rcos, p_rsin);
    mod_kernel<<<dim3(6 * Dm / 8, NB), 256>>>(cond, adaln_w, adaln_b, p_mod);
    ln_mod_kernel<<<MR, 256>>>(x, ln_pre_w, ln_pre_b, p_mod, 0, Dm, p_hxnorm);

    // K/V (4 sources) + Q + adapter hidden, one batched launch
    kvq_kernel<<<dim3(8, 16, 12), 256, GEMM_SMEM>>>(
        p_kcat, p_vcat, p_q0, k_b, v_b, q_proj_b, qa_b);

    // adapter out (batched over 3)
    adapter_o_kernel<<<dim3(8, 16, 3), 256, GEMM_SMEM>>>(qa_out_b, p_qad);

    // QK-norm + RoPE (single merged launch)
    qkpost_all_kernel<<<4 * MR + NB * KTOT, 256>>>(
        p_q0, p_qad, p_kcat, qn_w, kn_w, p_rcos, p_rsin);

    // flash attention (tf32 mma, fp16 output)
    flash_mma_kernel<<<dim3(Tq / 128, NH, NB), 256, FLASH_SMEM>>>(
        p_q0, p_qad, p_qad + (size_t)MR * Dm, p_qad + (size_t)2 * MR * Dm,
        p_kcat, p_vcat, temps, sbias, gating, p_hattn);

    // o-proj + residual + gate_attn
    oproj_kernel<<<dim3(8, 16), 256, GEMM_SMEM>>>(o_b, p_xa, x, p_mod);

    // FFN
    ln_mod_kernel<<<MR, 256>>>(p_xa, ffn_ln_w, ffn_ln_b, p_mod, 3 * Dm, 4 * Dm, p_hln);
    ffn1_kernel<<<dim3(32, 16), 256, GEMM_SMEM>>>(ffn_b1);
    ffn2_kernel<<<dim3(8, 16), 256, GEMM_SMEM>>>(ffn_b2, out, p_xa, p_mod);
}